// round 1
// baseline (speedup 1.0000x reference)
#include <cuda_runtime.h>
#include <math.h>

#define HH 64
#define WW 64
#define HW 4096
#define HIDC 128
#define BB 4
#define OO 8
#define CC 256

// Scratch (device globals; allocation is forbidden)
__device__ float g_states0[BB*OO*HIDC*HW];   // 64 MB
__device__ float g_states1[BB*OO*HIDC*HW];   // 64 MB
__device__ float g_S[BB*HIDC*HW];            // 8 MB
__device__ float g_T[BB*HIDC*HW];            // 8 MB
__device__ float g_base[BB*HIDC*HW];         // 8 MB
__device__ float g_rbase[BB*HW];
__device__ float g_Wd[HIDC*HIDC*9];          // W1 - W2

// ---------------------------------------------------------------------------
// Workhorse: 3x3 SAME conv, COUT=128. Block: (32,8)=256 thr, 32x32 px tile,
// 8 oc per block, per-thread micro-tile = 1x4 pixels x 8 oc (32 accumulators).
// Input channels processed in chunks of 4 held in smem.
// grid = (4 spatial tiles, 16 oc blocks, nImg)
// ---------------------------------------------------------------------------
template<int CIN>
__global__ void __launch_bounds__(256, 2)
conv3x3_k(const float* __restrict__ in, long inImgStride,
          const float* __restrict__ wgt, int wld, int icOff,
          const float* __restrict__ bias,
          const float* __restrict__ addend, int addDiv,
          float* __restrict__ out, int doRelu)
{
    __shared__ float insm[4*34*34];
    __shared__ float wsm[4*8*9];

    const int tx  = threadIdx.x;            // 0..31 (x within tile)
    const int ty  = threadIdx.y;            // 0..7  (y group of 4)
    const int tid = ty*32 + tx;
    const int img = blockIdx.z;
    const int ocBase = blockIdx.y * 8;
    const int tx0 = (blockIdx.x & 1) * 32;
    const int ty0 = (blockIdx.x >> 1) * 32;
    const float* inImg = in + (long)img * inImgStride;

    float acc[8][4];
    #pragma unroll
    for (int a=0;a<8;a++)
        #pragma unroll
        for (int i=0;i<4;i++) acc[a][i]=0.f;

    for (int ic0 = 0; ic0 < CIN; ic0 += 4) {
        __syncthreads();
        // load 34x34 halo tile for 4 input channels (coalesced, zero-padded)
        #pragma unroll
        for (int ci=0; ci<4; ci++) {
            const float* src = inImg + (long)(ic0+ci)*HW;
            for (int t = tid; t < 34*34; t += 256) {
                int yy = t / 34, xx = t - yy*34;
                int gy = ty0 - 1 + yy, gx = tx0 - 1 + xx;
                float v = 0.f;
                if ((unsigned)gy < 64u && (unsigned)gx < 64u) v = src[gy*64+gx];
                insm[(ci*34+yy)*34 + xx] = v;
            }
        }
        // load weights for this chunk: 4 cin x 8 oc x 9
        for (int t = tid; t < 288; t += 256) {
            int ci = t / 72, r = t % 72, oc = r/9, k = r%9;
            wsm[(ci*8+oc)*9+k] = wgt[((long)(ocBase+oc)*wld + icOff + ic0 + ci)*9 + k];
        }
        __syncthreads();
        #pragma unroll
        for (int ci=0; ci<4; ci++) {
            float r[6][3];
            #pragma unroll
            for (int i=0;i<6;i++)
                #pragma unroll
                for (int j=0;j<3;j++)
                    r[i][j] = insm[(ci*34 + 4*ty + i)*34 + tx + j];
            #pragma unroll
            for (int oc=0; oc<8; oc++) {
                float w[9];
                #pragma unroll
                for (int k=0;k<9;k++) w[k] = wsm[(ci*8+oc)*9+k];
                #pragma unroll
                for (int i=0;i<4;i++) {
                    float s = acc[oc][i];
                    s = fmaf(w[0], r[i  ][0], s);
                    s = fmaf(w[1], r[i  ][1], s);
                    s = fmaf(w[2], r[i  ][2], s);
                    s = fmaf(w[3], r[i+1][0], s);
                    s = fmaf(w[4], r[i+1][1], s);
                    s = fmaf(w[5], r[i+1][2], s);
                    s = fmaf(w[6], r[i+2][0], s);
                    s = fmaf(w[7], r[i+2][1], s);
                    s = fmaf(w[8], r[i+2][2], s);
                    acc[oc][i] = s;
                }
            }
        }
    }
    // epilogue
    const int addImg = addDiv ? (img / addDiv) : 0;
    #pragma unroll
    for (int oc=0; oc<8; oc++) {
        float bv = bias ? bias[ocBase+oc] : 0.f;
        #pragma unroll
        for (int i=0;i<4;i++) {
            int gy = ty0 + 4*ty + i, gx = tx0 + tx;
            long off = ((long)(ocBase+oc))*HW + gy*64 + gx;
            float v = acc[oc][i] + bv;
            if (addend) v += addend[(long)addImg*HIDC*HW + off];
            if (doRelu) v = fmaxf(v, 0.f);
            out[(long)img*HIDC*HW + off] = v;
        }
    }
}

// ---------------------------------------------------------------------------
// Enc per-object: states = relu(base + conv3x3(mask, enc_w[:,256])) ; Cin=1
// grid (16, 32) x 256 thr, 1 px/thread, loop 128 oc
// ---------------------------------------------------------------------------
__global__ void __launch_bounds__(256) enc_obj_k(
    const float* __restrict__ masks, const float* __restrict__ enc_w,
    const float* __restrict__ base, float* __restrict__ states)
{
    __shared__ float wm[HIDC*9];
    const int tid = threadIdx.x;
    const int img = blockIdx.y;                 // 0..31
    const int p   = blockIdx.x*256 + tid;       // 0..4095
    for (int t = tid; t < HIDC*9; t += 256) {
        int oc = t/9, k = t - oc*9;
        wm[t] = enc_w[((long)oc*257 + 256)*9 + k];
    }
    __syncthreads();
    const int y = p >> 6, x = p & 63;
    float m[3][3];
    #pragma unroll
    for (int i=0;i<3;i++)
        #pragma unroll
        for (int j=0;j<3;j++) {
            int gy=y-1+i, gx=x-1+j;
            m[i][j] = ((unsigned)gy<64u && (unsigned)gx<64u)
                        ? masks[(long)img*HW + gy*64+gx] : 0.f;
        }
    const int b = img >> 3;
    const float* bimg = base + (long)b*HIDC*HW;
    float* simg = states + (long)img*HIDC*HW;
    #pragma unroll 4
    for (int oc=0; oc<HIDC; oc++) {
        float a = bimg[oc*HW + p];
        #pragma unroll
        for (int k=0;k<9;k++) a = fmaf(wm[oc*9+k], m[k/3][k%3], a);
        simg[oc*HW + p] = fmaxf(a, 0.f);
    }
}

// Sum over objects: S[b,c,p] = sum_o states[b,o,c,p]
__global__ void sumO_k(const float* __restrict__ states, float* __restrict__ S)
{
    int idx = blockIdx.x*256 + threadIdx.x;
    if (idx >= BB*HIDC*HW) return;
    int b = idx / (HIDC*HW);
    int r = idx - b*(HIDC*HW);
    const float* p = states + (long)b*OO*HIDC*HW + r;
    float s = 0.f;
    #pragma unroll
    for (int o=0;o<OO;o++) s += p[(long)o*HIDC*HW];
    S[idx] = s;
}

// Wd = gcn_w[:, :128] - gcn_w[:, 128:]
__global__ void wd_k(const float* __restrict__ gcn_w, float* __restrict__ wd)
{
    int idx = blockIdx.x*256 + threadIdx.x;
    if (idx >= HIDC*HIDC*9) return;
    int oc = idx / (HIDC*9);
    int r  = idx - oc*(HIDC*9);
    wd[idx] = gcn_w[(long)oc*2*HIDC*9 + r] - gcn_w[(long)oc*2*HIDC*9 + HIDC*9 + r];
}

// Readout base: rbase[b,p] = ro_b + conv3x3(feats_b, ro_w[:, :256])
// grid (16, 4) x 256 thr (16x16 px tile), loop 256 cin
__global__ void __launch_bounds__(256) ro_base_k(
    const float* __restrict__ feats, const float* __restrict__ ro_w,
    const float* __restrict__ ro_b, float* __restrict__ rbase)
{
    __shared__ float tile[18*18];
    __shared__ float ws[CC*9];
    const int tid = threadIdx.x;
    const int img = blockIdx.y;
    const int tx0 = (blockIdx.x & 3)*16, ty0 = (blockIdx.x >> 2)*16;
    for (int t=tid; t<CC*9; t+=256) ws[t] = ro_w[t];
    const int px = tid & 15, py = tid >> 4;
    float acc = ro_b[0];
    const float* fimg = feats + (long)img*CC*HW;
    for (int ic=0; ic<CC; ic++) {
        __syncthreads();
        for (int t=tid; t<18*18; t+=256) {
            int yy=t/18, xx=t-yy*18;
            int gy=ty0-1+yy, gx=tx0-1+xx;
            tile[t] = ((unsigned)gy<64u && (unsigned)gx<64u)
                        ? fimg[(long)ic*HW + gy*64+gx] : 0.f;
        }
        __syncthreads();
        #pragma unroll
        for (int k=0;k<9;k++)
            acc = fmaf(ws[ic*9+k], tile[(py+k/3)*18 + px + (k%3)], acc);
    }
    rbase[(long)img*HW + (ty0+py)*64 + tx0+px] = acc;
}

// Readout per-object: out = sigmoid(rbase[b] + conv3x3(states, ro_w[:,256:384]))
__global__ void __launch_bounds__(256) ro_obj_k(
    const float* __restrict__ states, const float* __restrict__ ro_w,
    const float* __restrict__ rbase, float* __restrict__ outp)
{
    __shared__ float tile[18*18];
    __shared__ float ws[HIDC*9];
    const int tid = threadIdx.x;
    const int img = blockIdx.y;                  // 0..31
    const int tx0 = (blockIdx.x & 3)*16, ty0 = (blockIdx.x >> 2)*16;
    for (int t=tid; t<HIDC*9; t+=256) ws[t] = ro_w[(long)CC*9 + t];
    const int px = tid & 15, py = tid >> 4;
    float acc = 0.f;
    const float* simg = states + (long)img*HIDC*HW;
    for (int ic=0; ic<HIDC; ic++) {
        __syncthreads();
        for (int t=tid; t<18*18; t+=256) {
            int yy=t/18, xx=t-yy*18;
            int gy=ty0-1+yy, gx=tx0-1+xx;
            tile[t] = ((unsigned)gy<64u && (unsigned)gx<64u)
                        ? simg[(long)ic*HW + gy*64+gx] : 0.f;
        }
        __syncthreads();
        #pragma unroll
        for (int k=0;k<9;k++)
            acc = fmaf(ws[ic*9+k], tile[(py+k/3)*18 + px + (k%3)], acc);
    }
    const int b = img >> 3;
    float z = acc + rbase[(long)b*HW + (ty0+py)*64 + tx0+px];
    outp[(long)img*HW + (ty0+py)*64 + tx0+px] = 1.f/(1.f + expf(-z));
}

// ---------------------------------------------------------------------------
extern "C" void kernel_launch(void* const* d_in, const int* in_sizes, int n_in,
                              void* d_out, int out_size)
{
    const float* feats = (const float*)d_in[0];  // [4,256,64,64]
    const float* masks = (const float*)d_in[1];  // [4,8,64,64]
    const float* enc_w = (const float*)d_in[4];  // [128,257,3,3]
    const float* enc_b = (const float*)d_in[5];  // [128]
    const float* gcn_w = (const float*)d_in[6];  // [128,256,3,3]
    const float* gcn_b = (const float*)d_in[7];  // [128]
    const float* ro_w  = (const float*)d_in[8];  // [1,384,3,3]
    const float* ro_b  = (const float*)d_in[9];  // [1]
    float* outp = (float*)d_out;

    float *st0, *st1, *S, *T, *base, *rbase, *wd;
    cudaGetSymbolAddress((void**)&st0,   g_states0);
    cudaGetSymbolAddress((void**)&st1,   g_states1);
    cudaGetSymbolAddress((void**)&S,     g_S);
    cudaGetSymbolAddress((void**)&T,     g_T);
    cudaGetSymbolAddress((void**)&base,  g_base);
    cudaGetSymbolAddress((void**)&rbase, g_rbase);
    cudaGetSymbolAddress((void**)&wd,    g_Wd);

    dim3 cb(32, 8);

    // Wd = W1 - W2
    wd_k<<<(HIDC*HIDC*9+255)/256, 256>>>(gcn_w, wd);

    // enc base (shared across objects): conv(feats, enc_w[:, :256]) + enc_b
    conv3x3_k<256><<<dim3(4,16,BB), cb>>>(feats, (long)CC*HW, enc_w, 257, 0,
                                          enc_b, nullptr, 0, base, 0);
    // enc per-object: relu(base + conv(mask, enc_w[:, 256]))
    enc_obj_k<<<dim3(16, BB*OO), 256>>>(masks, enc_w, base, st0);

    float* cur = st0; float* nxt = st1;
    for (int s = 0; s < 2; s++) {
        sumO_k<<<(BB*HIDC*HW+255)/256, 256>>>(cur, S);
        // T = conv(S, W2) + gcn_b   (per batch image)
        conv3x3_k<128><<<dim3(4,16,BB), cb>>>(S, (long)HIDC*HW, gcn_w, 256, 128,
                                              gcn_b, nullptr, 0, T, 0);
        // states' = relu(conv(states, Wd) + T)   (per object image)
        conv3x3_k<128><<<dim3(4,16,BB*OO), cb>>>(cur, (long)HIDC*HW, wd, 128, 0,
                                                 nullptr, T, OO, nxt, 1);
        float* tmp = cur; cur = nxt; nxt = tmp;
    }

    // readout
    ro_base_k<<<dim3(16, BB), 256>>>(feats, ro_w, ro_b, rbase);
    ro_obj_k<<<dim3(16, BB*OO), 256>>>(cur, ro_w, rbase, outp);
}

// round 2
// speedup vs baseline: 1.5022x; 1.5022x over previous
#include <cuda_runtime.h>
#include <math.h>

#define HH 64
#define WW 64
#define HW 4096
#define HIDC 128
#define BB 4
#define OO 8
#define CC 256

// Scratch (device globals; allocation is forbidden)
__device__ float g_states0[BB*OO*HIDC*HW];   // 64 MB
__device__ float g_states1[BB*OO*HIDC*HW];   // 64 MB
__device__ float g_S[BB*HIDC*HW];            // 8 MB
__device__ float g_T[BB*HIDC*HW];            // 8 MB
__device__ float g_base[BB*HIDC*HW];         // 8 MB
__device__ float g_rbase[BB*HW];
__device__ float g_Wd[HIDC*HIDC*9];          // W1 - W2

// ---------------------------------------------------------------------------
// Workhorse: 3x3 SAME conv, COUT=128. Block: (32,8)=256 thr, 32x32 px tile,
// 8 oc per block, per-thread micro-tile = 1x4 pixels x 8 oc (32 accumulators).
// Input channels processed in chunks of 4 held in smem.
// grid = (4 spatial tiles, 16 oc blocks, nImg)
// ---------------------------------------------------------------------------
template<int CIN>
__global__ void __launch_bounds__(256, 2)
conv3x3_k(const float* __restrict__ in, long inImgStride,
          const float* __restrict__ wgt, int wld, int icOff,
          const float* __restrict__ bias,
          const float* __restrict__ addend, int addDiv,
          float* __restrict__ out, int doRelu)
{
    __shared__ float insm[4*34*34];
    __shared__ float wsm[4*8*9];

    const int tx  = threadIdx.x;            // 0..31 (x within tile)
    const int ty  = threadIdx.y;            // 0..7  (y group of 4)
    const int tid = ty*32 + tx;
    const int img = blockIdx.z;
    const int ocBase = blockIdx.y * 8;
    const int tx0 = (blockIdx.x & 1) * 32;
    const int ty0 = (blockIdx.x >> 1) * 32;
    const float* inImg = in + (long)img * inImgStride;

    float acc[8][4];
    #pragma unroll
    for (int a=0;a<8;a++)
        #pragma unroll
        for (int i=0;i<4;i++) acc[a][i]=0.f;

    for (int ic0 = 0; ic0 < CIN; ic0 += 4) {
        __syncthreads();
        // load 34x34 halo tile for 4 input channels (coalesced, zero-padded)
        #pragma unroll
        for (int ci=0; ci<4; ci++) {
            const float* src = inImg + (long)(ic0+ci)*HW;
            for (int t = tid; t < 34*34; t += 256) {
                int yy = t / 34, xx = t - yy*34;
                int gy = ty0 - 1 + yy, gx = tx0 - 1 + xx;
                float v = 0.f;
                if ((unsigned)gy < 64u && (unsigned)gx < 64u) v = src[gy*64+gx];
                insm[(ci*34+yy)*34 + xx] = v;
            }
        }
        // load weights for this chunk: 4 cin x 8 oc x 9
        for (int t = tid; t < 288; t += 256) {
            int ci = t / 72, r = t % 72, oc = r/9, k = r%9;
            wsm[(ci*8+oc)*9+k] = wgt[((long)(ocBase+oc)*wld + icOff + ic0 + ci)*9 + k];
        }
        __syncthreads();
        #pragma unroll
        for (int ci=0; ci<4; ci++) {
            float r[6][3];
            #pragma unroll
            for (int i=0;i<6;i++)
                #pragma unroll
                for (int j=0;j<3;j++)
                    r[i][j] = insm[(ci*34 + 4*ty + i)*34 + tx + j];
            #pragma unroll
            for (int oc=0; oc<8; oc++) {
                float w[9];
                #pragma unroll
                for (int k=0;k<9;k++) w[k] = wsm[(ci*8+oc)*9+k];
                #pragma unroll
                for (int i=0;i<4;i++) {
                    float s = acc[oc][i];
                    s = fmaf(w[0], r[i  ][0], s);
                    s = fmaf(w[1], r[i  ][1], s);
                    s = fmaf(w[2], r[i  ][2], s);
                    s = fmaf(w[3], r[i+1][0], s);
                    s = fmaf(w[4], r[i+1][1], s);
                    s = fmaf(w[5], r[i+1][2], s);
                    s = fmaf(w[6], r[i+2][0], s);
                    s = fmaf(w[7], r[i+2][1], s);
                    s = fmaf(w[8], r[i+2][2], s);
                    acc[oc][i] = s;
                }
            }
        }
    }
    // epilogue
    const int addImg = addDiv ? (img / addDiv) : 0;
    #pragma unroll
    for (int oc=0; oc<8; oc++) {
        float bv = bias ? bias[ocBase+oc] : 0.f;
        #pragma unroll
        for (int i=0;i<4;i++) {
            int gy = ty0 + 4*ty + i, gx = tx0 + tx;
            long off = ((long)(ocBase+oc))*HW + gy*64 + gx;
            float v = acc[oc][i] + bv;
            if (addend) v += addend[(long)addImg*HIDC*HW + off];
            if (doRelu) v = fmaxf(v, 0.f);
            out[(long)img*HIDC*HW + off] = v;
        }
    }
}

// ---------------------------------------------------------------------------
// Enc per-object: states = relu(base + conv3x3(mask, enc_w[:,256])) ; Cin=1
// grid (16, 32) x 256 thr, 1 px/thread, loop 128 oc
// ---------------------------------------------------------------------------
__global__ void __launch_bounds__(256) enc_obj_k(
    const float* __restrict__ masks, const float* __restrict__ enc_w,
    const float* __restrict__ base, float* __restrict__ states)
{
    __shared__ float wm[HIDC*9];
    const int tid = threadIdx.x;
    const int img = blockIdx.y;                 // 0..31
    const int p   = blockIdx.x*256 + tid;       // 0..4095
    for (int t = tid; t < HIDC*9; t += 256) {
        int oc = t/9, k = t - oc*9;
        wm[t] = enc_w[((long)oc*257 + 256)*9 + k];
    }
    __syncthreads();
    const int y = p >> 6, x = p & 63;
    float m[3][3];
    #pragma unroll
    for (int i=0;i<3;i++)
        #pragma unroll
        for (int j=0;j<3;j++) {
            int gy=y-1+i, gx=x-1+j;
            m[i][j] = ((unsigned)gy<64u && (unsigned)gx<64u)
                        ? masks[(long)img*HW + gy*64+gx] : 0.f;
        }
    const int b = img >> 3;
    const float* bimg = base + (long)b*HIDC*HW;
    float* simg = states + (long)img*HIDC*HW;
    #pragma unroll 4
    for (int oc=0; oc<HIDC; oc++) {
        float a = bimg[oc*HW + p];
        #pragma unroll
        for (int k=0;k<9;k++) a = fmaf(wm[oc*9+k], m[k/3][k%3], a);
        simg[oc*HW + p] = fmaxf(a, 0.f);
    }
}

// Sum over objects: S[b,c,p] = sum_o states[b,o,c,p]
__global__ void sumO_k(const float* __restrict__ states, float* __restrict__ S)
{
    int idx = blockIdx.x*256 + threadIdx.x;
    if (idx >= BB*HIDC*HW) return;
    int b = idx / (HIDC*HW);
    int r = idx - b*(HIDC*HW);
    const float* p = states + (long)b*OO*HIDC*HW + r;
    float s = 0.f;
    #pragma unroll
    for (int o=0;o<OO;o++) s += p[(long)o*HIDC*HW];
    S[idx] = s;
}

// Wd = gcn_w[:, :128] - gcn_w[:, 128:]
__global__ void wd_k(const float* __restrict__ gcn_w, float* __restrict__ wd)
{
    int idx = blockIdx.x*256 + threadIdx.x;
    if (idx >= HIDC*HIDC*9) return;
    int oc = idx / (HIDC*9);
    int r  = idx - oc*(HIDC*9);
    wd[idx] = gcn_w[(long)oc*2*HIDC*9 + r] - gcn_w[(long)oc*2*HIDC*9 + HIDC*9 + r];
}

// Readout base: rbase[b,p] = ro_b + conv3x3(feats_b, ro_w[:, :256])
// grid (16, 4) x 256 thr (16x16 px tile), loop 256 cin
__global__ void __launch_bounds__(256) ro_base_k(
    const float* __restrict__ feats, const float* __restrict__ ro_w,
    const float* __restrict__ ro_b, float* __restrict__ rbase)
{
    __shared__ float tile[18*18];
    __shared__ float ws[CC*9];
    const int tid = threadIdx.x;
    const int img = blockIdx.y;
    const int tx0 = (blockIdx.x & 3)*16, ty0 = (blockIdx.x >> 2)*16;
    for (int t=tid; t<CC*9; t+=256) ws[t] = ro_w[t];
    const int px = tid & 15, py = tid >> 4;
    float acc = ro_b[0];
    const float* fimg = feats + (long)img*CC*HW;
    for (int ic=0; ic<CC; ic++) {
        __syncthreads();
        for (int t=tid; t<18*18; t+=256) {
            int yy=t/18, xx=t-yy*18;
            int gy=ty0-1+yy, gx=tx0-1+xx;
            tile[t] = ((unsigned)gy<64u && (unsigned)gx<64u)
                        ? fimg[(long)ic*HW + gy*64+gx] : 0.f;
        }
        __syncthreads();
        #pragma unroll
        for (int k=0;k<9;k++)
            acc = fmaf(ws[ic*9+k], tile[(py+k/3)*18 + px + (k%3)], acc);
    }
    rbase[(long)img*HW + (ty0+py)*64 + tx0+px] = acc;
}

// Readout per-object: out = sigmoid(rbase[b] + conv3x3(states, ro_w[:,256:384]))
__global__ void __launch_bounds__(256) ro_obj_k(
    const float* __restrict__ states, const float* __restrict__ ro_w,
    const float* __restrict__ rbase, float* __restrict__ outp)
{
    __shared__ float tile[18*18];
    __shared__ float ws[HIDC*9];
    const int tid = threadIdx.x;
    const int img = blockIdx.y;                  // 0..31
    const int tx0 = (blockIdx.x & 3)*16, ty0 = (blockIdx.x >> 2)*16;
    for (int t=tid; t<HIDC*9; t+=256) ws[t] = ro_w[(long)CC*9 + t];
    const int px = tid & 15, py = tid >> 4;
    float acc = 0.f;
    const float* simg = states + (long)img*HIDC*HW;
    for (int ic=0; ic<HIDC; ic++) {
        __syncthreads();
        for (int t=tid; t<18*18; t+=256) {
            int yy=t/18, xx=t-yy*18;
            int gy=ty0-1+yy, gx=tx0-1+xx;
            tile[t] = ((unsigned)gy<64u && (unsigned)gx<64u)
                        ? simg[(long)ic*HW + gy*64+gx] : 0.f;
        }
        __syncthreads();
        #pragma unroll
        for (int k=0;k<9;k++)
            acc = fmaf(ws[ic*9+k], tile[(py+k/3)*18 + px + (k%3)], acc);
    }
    const int b = img >> 3;
    float z = acc + rbase[(long)b*HW + (ty0+py)*64 + tx0+px];
    outp[(long)img*HW + (ty0+py)*64 + tx0+px] = 1.f/(1.f + expf(-z));
}

// ---------------------------------------------------------------------------
extern "C" void kernel_launch(void* const* d_in, const int* in_sizes, int n_in,
                              void* d_out, int out_size)
{
    const float* feats = (const float*)d_in[0];  // [4,256,64,64]
    const float* masks = (const float*)d_in[1];  // [4,8,64,64]
    const float* enc_w = (const float*)d_in[4];  // [128,257,3,3]
    const float* enc_b = (const float*)d_in[5];  // [128]
    const float* gcn_w = (const float*)d_in[6];  // [128,256,3,3]
    const float* gcn_b = (const float*)d_in[7];  // [128]
    const float* ro_w  = (const float*)d_in[8];  // [1,384,3,3]
    const float* ro_b  = (const float*)d_in[9];  // [1]
    float* outp = (float*)d_out;

    float *st0, *st1, *S, *T, *base, *rbase, *wd;
    cudaGetSymbolAddress((void**)&st0,   g_states0);
    cudaGetSymbolAddress((void**)&st1,   g_states1);
    cudaGetSymbolAddress((void**)&S,     g_S);
    cudaGetSymbolAddress((void**)&T,     g_T);
    cudaGetSymbolAddress((void**)&base,  g_base);
    cudaGetSymbolAddress((void**)&rbase, g_rbase);
    cudaGetSymbolAddress((void**)&wd,    g_Wd);

    dim3 cb(32, 8);

    // Wd = W1 - W2
    wd_k<<<(HIDC*HIDC*9+255)/256, 256>>>(gcn_w, wd);

    // enc base (shared across objects): conv(feats, enc_w[:, :256]) + enc_b
    conv3x3_k<256><<<dim3(4,16,BB), cb>>>(feats, (long)CC*HW, enc_w, 257, 0,
                                          enc_b, nullptr, 0, base, 0);
    // enc per-object: relu(base + conv(mask, enc_w[:, 256]))
    enc_obj_k<<<dim3(16, BB*OO), 256>>>(masks, enc_w, base, st0);

    float* cur = st0; float* nxt = st1;
    for (int s = 0; s < 2; s++) {
        sumO_k<<<(BB*HIDC*HW+255)/256, 256>>>(cur, S);
        // T = conv(S, W2) + gcn_b   (per batch image)
        conv3x3_k<128><<<dim3(4,16,BB), cb>>>(S, (long)HIDC*HW, gcn_w, 256, 128,
                                              gcn_b, nullptr, 0, T, 0);
        // states' = relu(conv(states, Wd) + T)   (per object image)
        conv3x3_k<128><<<dim3(4,16,BB*OO), cb>>>(cur, (long)HIDC*HW, wd, 128, 0,
                                                 nullptr, T, OO, nxt, 1);
        float* tmp = cur; cur = nxt; nxt = tmp;
    }

    // readout
    ro_base_k<<<dim3(16, BB), 256>>>(feats, ro_w, ro_b, rbase);
    ro_obj_k<<<dim3(16, BB*OO), 256>>>(cur, ro_w, rbase, outp);
}

// round 3
// speedup vs baseline: 1.5549x; 1.0351x over previous
#include <cuda_runtime.h>
#include <math.h>

#define HH 64
#define WW 64
#define HW 4096
#define HIDC 128
#define BB 4
#define OO 8
#define CC 256

// Scratch (device globals; allocation is forbidden)
__device__ float g_states0[BB*OO*HIDC*HW];   // 64 MB
__device__ float g_states1[BB*OO*HIDC*HW];   // 64 MB
__device__ float g_S[BB*HIDC*HW];            // 8 MB
__device__ float g_T[BB*HIDC*HW];            // 8 MB
__device__ float g_base[BB*HIDC*HW];         // 8 MB
__device__ float g_rbase[BB*HW];
__device__ float g_Wd[HIDC*HIDC*9];          // W1 - W2

// ---------------------------------------------------------------------------
// Workhorse: 3x3 SAME conv, COUT=128. Block: (32,8)=256 thr, 32x32 px tile,
// 8 oc per block, per-thread micro-tile = 1x4 pixels x 8 oc (32 accumulators).
// Input channels processed in chunks of 4 held in smem.
// grid = (4 spatial tiles, 16 oc blocks, nImg)
// ---------------------------------------------------------------------------
template<int CIN>
__global__ void __launch_bounds__(256, 2)
conv3x3_k(const float* __restrict__ in, long inImgStride,
          const float* __restrict__ wgt, int wld, int icOff,
          const float* __restrict__ bias,
          const float* __restrict__ addend, int addDiv,
          float* __restrict__ out, int doRelu)
{
    __shared__ float insm[4*34*34];
    __shared__ float wsm[4*8*9];

    const int tx  = threadIdx.x;            // 0..31 (x within tile)
    const int ty  = threadIdx.y;            // 0..7  (y group of 4)
    const int tid = ty*32 + tx;
    const int img = blockIdx.z;
    const int ocBase = blockIdx.y * 8;
    const int tx0 = (blockIdx.x & 1) * 32;
    const int ty0 = (blockIdx.x >> 1) * 32;
    const float* inImg = in + (long)img * inImgStride;

    float acc[8][4];
    #pragma unroll
    for (int a=0;a<8;a++)
        #pragma unroll
        for (int i=0;i<4;i++) acc[a][i]=0.f;

    for (int ic0 = 0; ic0 < CIN; ic0 += 4) {
        __syncthreads();
        // load 34x34 halo tile for 4 input channels (coalesced, zero-padded)
        #pragma unroll
        for (int ci=0; ci<4; ci++) {
            const float* src = inImg + (long)(ic0+ci)*HW;
            for (int t = tid; t < 34*34; t += 256) {
                int yy = t / 34, xx = t - yy*34;
                int gy = ty0 - 1 + yy, gx = tx0 - 1 + xx;
                float v = 0.f;
                if ((unsigned)gy < 64u && (unsigned)gx < 64u) v = src[gy*64+gx];
                insm[(ci*34+yy)*34 + xx] = v;
            }
        }
        // load weights for this chunk: 4 cin x 8 oc x 9
        for (int t = tid; t < 288; t += 256) {
            int ci = t / 72, r = t % 72, oc = r/9, k = r%9;
            wsm[(ci*8+oc)*9+k] = wgt[((long)(ocBase+oc)*wld + icOff + ic0 + ci)*9 + k];
        }
        __syncthreads();
        #pragma unroll
        for (int ci=0; ci<4; ci++) {
            float r[6][3];
            #pragma unroll
            for (int i=0;i<6;i++)
                #pragma unroll
                for (int j=0;j<3;j++)
                    r[i][j] = insm[(ci*34 + 4*ty + i)*34 + tx + j];
            #pragma unroll
            for (int oc=0; oc<8; oc++) {
                float w[9];
                #pragma unroll
                for (int k=0;k<9;k++) w[k] = wsm[(ci*8+oc)*9+k];
                #pragma unroll
                for (int i=0;i<4;i++) {
                    float s = acc[oc][i];
                    s = fmaf(w[0], r[i  ][0], s);
                    s = fmaf(w[1], r[i  ][1], s);
                    s = fmaf(w[2], r[i  ][2], s);
                    s = fmaf(w[3], r[i+1][0], s);
                    s = fmaf(w[4], r[i+1][1], s);
                    s = fmaf(w[5], r[i+1][2], s);
                    s = fmaf(w[6], r[i+2][0], s);
                    s = fmaf(w[7], r[i+2][1], s);
                    s = fmaf(w[8], r[i+2][2], s);
                    acc[oc][i] = s;
                }
            }
        }
    }
    // epilogue
    const int addImg = addDiv ? (img / addDiv) : 0;
    #pragma unroll
    for (int oc=0; oc<8; oc++) {
        float bv = bias ? bias[ocBase+oc] : 0.f;
        #pragma unroll
        for (int i=0;i<4;i++) {
            int gy = ty0 + 4*ty + i, gx = tx0 + tx;
            long off = ((long)(ocBase+oc))*HW + gy*64 + gx;
            float v = acc[oc][i] + bv;
            if (addend) v += addend[(long)addImg*HIDC*HW + off];
            if (doRelu) v = fmaxf(v, 0.f);
            out[(long)img*HIDC*HW + off] = v;
        }
    }
}

// ---------------------------------------------------------------------------
// Enc per-object: states = relu(base + conv3x3(mask, enc_w[:,256])) ; Cin=1
// grid (16, 32) x 256 thr, 1 px/thread, loop 128 oc
// ---------------------------------------------------------------------------
__global__ void __launch_bounds__(256) enc_obj_k(
    const float* __restrict__ masks, const float* __restrict__ enc_w,
    const float* __restrict__ base, float* __restrict__ states)
{
    __shared__ float wm[HIDC*9];
    const int tid = threadIdx.x;
    const int img = blockIdx.y;                 // 0..31
    const int p   = blockIdx.x*256 + tid;       // 0..4095
    for (int t = tid; t < HIDC*9; t += 256) {
        int oc = t/9, k = t - oc*9;
        wm[t] = enc_w[((long)oc*257 + 256)*9 + k];
    }
    __syncthreads();
    const int y = p >> 6, x = p & 63;
    float m[3][3];
    #pragma unroll
    for (int i=0;i<3;i++)
        #pragma unroll
        for (int j=0;j<3;j++) {
            int gy=y-1+i, gx=x-1+j;
            m[i][j] = ((unsigned)gy<64u && (unsigned)gx<64u)
                        ? masks[(long)img*HW + gy*64+gx] : 0.f;
        }
    const int b = img >> 3;
    const float* bimg = base + (long)b*HIDC*HW;
    float* simg = states + (long)img*HIDC*HW;
    #pragma unroll 4
    for (int oc=0; oc<HIDC; oc++) {
        float a = bimg[oc*HW + p];
        #pragma unroll
        for (int k=0;k<9;k++) a = fmaf(wm[oc*9+k], m[k/3][k%3], a);
        simg[oc*HW + p] = fmaxf(a, 0.f);
    }
}

// Sum over objects: S[b,c,p] = sum_o states[b,o,c,p]
__global__ void sumO_k(const float* __restrict__ states, float* __restrict__ S)
{
    int idx = blockIdx.x*256 + threadIdx.x;
    if (idx >= BB*HIDC*HW) return;
    int b = idx / (HIDC*HW);
    int r = idx - b*(HIDC*HW);
    const float* p = states + (long)b*OO*HIDC*HW + r;
    float s = 0.f;
    #pragma unroll
    for (int o=0;o<OO;o++) s += p[(long)o*HIDC*HW];
    S[idx] = s;
}

// Wd = gcn_w[:, :128] - gcn_w[:, 128:]
__global__ void wd_k(const float* __restrict__ gcn_w, float* __restrict__ wd)
{
    int idx = blockIdx.x*256 + threadIdx.x;
    if (idx >= HIDC*HIDC*9) return;
    int oc = idx / (HIDC*9);
    int r  = idx - oc*(HIDC*9);
    wd[idx] = gcn_w[(long)oc*2*HIDC*9 + r] - gcn_w[(long)oc*2*HIDC*9 + HIDC*9 + r];
}

// Readout base: rbase[b,p] = ro_b + conv3x3(feats_b, ro_w[:, :256])
// grid (16, 4) x 256 thr (16x16 px tile), loop 256 cin
__global__ void __launch_bounds__(256) ro_base_k(
    const float* __restrict__ feats, const float* __restrict__ ro_w,
    const float* __restrict__ ro_b, float* __restrict__ rbase)
{
    __shared__ float tile[18*18];
    __shared__ float ws[CC*9];
    const int tid = threadIdx.x;
    const int img = blockIdx.y;
    const int tx0 = (blockIdx.x & 3)*16, ty0 = (blockIdx.x >> 2)*16;
    for (int t=tid; t<CC*9; t+=256) ws[t] = ro_w[t];
    const int px = tid & 15, py = tid >> 4;
    float acc = ro_b[0];
    const float* fimg = feats + (long)img*CC*HW;
    for (int ic=0; ic<CC; ic++) {
        __syncthreads();
        for (int t=tid; t<18*18; t+=256) {
            int yy=t/18, xx=t-yy*18;
            int gy=ty0-1+yy, gx=tx0-1+xx;
            tile[t] = ((unsigned)gy<64u && (unsigned)gx<64u)
                        ? fimg[(long)ic*HW + gy*64+gx] : 0.f;
        }
        __syncthreads();
        #pragma unroll
        for (int k=0;k<9;k++)
            acc = fmaf(ws[ic*9+k], tile[(py+k/3)*18 + px + (k%3)], acc);
    }
    rbase[(long)img*HW + (ty0+py)*64 + tx0+px] = acc;
}

// Readout per-object: out = sigmoid(rbase[b] + conv3x3(states, ro_w[:,256:384]))
__global__ void __launch_bounds__(256) ro_obj_k(
    const float* __restrict__ states, const float* __restrict__ ro_w,
    const float* __restrict__ rbase, float* __restrict__ outp)
{
    __shared__ float tile[18*18];
    __shared__ float ws[HIDC*9];
    const int tid = threadIdx.x;
    const int img = blockIdx.y;                  // 0..31
    const int tx0 = (blockIdx.x & 3)*16, ty0 = (blockIdx.x >> 2)*16;
    for (int t=tid; t<HIDC*9; t+=256) ws[t] = ro_w[(long)CC*9 + t];
    const int px = tid & 15, py = tid >> 4;
    float acc = 0.f;
    const float* simg = states + (long)img*HIDC*HW;
    for (int ic=0; ic<HIDC; ic++) {
        __syncthreads();
        for (int t=tid; t<18*18; t+=256) {
            int yy=t/18, xx=t-yy*18;
            int gy=ty0-1+yy, gx=tx0-1+xx;
            tile[t] = ((unsigned)gy<64u && (unsigned)gx<64u)
                        ? simg[(long)ic*HW + gy*64+gx] : 0.f;
        }
        __syncthreads();
        #pragma unroll
        for (int k=0;k<9;k++)
            acc = fmaf(ws[ic*9+k], tile[(py+k/3)*18 + px + (k%3)], acc);
    }
    const int b = img >> 3;
    float z = acc + rbase[(long)b*HW + (ty0+py)*64 + tx0+px];
    outp[(long)img*HW + (ty0+py)*64 + tx0+px] = 1.f/(1.f + expf(-z));
}

// ---------------------------------------------------------------------------
extern "C" void kernel_launch(void* const* d_in, const int* in_sizes, int n_in,
                              void* d_out, int out_size)
{
    const float* feats = (const float*)d_in[0];  // [4,256,64,64]
    const float* masks = (const float*)d_in[1];  // [4,8,64,64]
    const float* enc_w = (const float*)d_in[4];  // [128,257,3,3]
    const float* enc_b = (const float*)d_in[5];  // [128]
    const float* gcn_w = (const float*)d_in[6];  // [128,256,3,3]
    const float* gcn_b = (const float*)d_in[7];  // [128]
    const float* ro_w  = (const float*)d_in[8];  // [1,384,3,3]
    const float* ro_b  = (const float*)d_in[9];  // [1]
    float* outp = (float*)d_out;

    float *st0, *st1, *S, *T, *base, *rbase, *wd;
    cudaGetSymbolAddress((void**)&st0,   g_states0);
    cudaGetSymbolAddress((void**)&st1,   g_states1);
    cudaGetSymbolAddress((void**)&S,     g_S);
    cudaGetSymbolAddress((void**)&T,     g_T);
    cudaGetSymbolAddress((void**)&base,  g_base);
    cudaGetSymbolAddress((void**)&rbase, g_rbase);
    cudaGetSymbolAddress((void**)&wd,    g_Wd);

    dim3 cb(32, 8);

    // Wd = W1 - W2
    wd_k<<<(HIDC*HIDC*9+255)/256, 256>>>(gcn_w, wd);

    // enc base (shared across objects): conv(feats, enc_w[:, :256]) + enc_b
    conv3x3_k<256><<<dim3(4,16,BB), cb>>>(feats, (long)CC*HW, enc_w, 257, 0,
                                          enc_b, nullptr, 0, base, 0);
    // enc per-object: relu(base + conv(mask, enc_w[:, 256]))
    enc_obj_k<<<dim3(16, BB*OO), 256>>>(masks, enc_w, base, st0);

    float* cur = st0; float* nxt = st1;
    for (int s = 0; s < 2; s++) {
        sumO_k<<<(BB*HIDC*HW+255)/256, 256>>>(cur, S);
        // T = conv(S, W2) + gcn_b   (per batch image)
        conv3x3_k<128><<<dim3(4,16,BB), cb>>>(S, (long)HIDC*HW, gcn_w, 256, 128,
                                              gcn_b, nullptr, 0, T, 0);
        // states' = relu(conv(states, Wd) + T)   (per object image)
        conv3x3_k<128><<<dim3(4,16,BB*OO), cb>>>(cur, (long)HIDC*HW, wd, 128, 0,
                                                 nullptr, T, OO, nxt, 1);
        float* tmp = cur; cur = nxt; nxt = tmp;
    }

    // readout
    ro_base_k<<<dim3(16, BB), 256>>>(feats, ro_w, ro_b, rbase);
    ro_obj_k<<<dim3(16, BB*OO), 256>>>(cur, ro_w, rbase, outp);
}

// round 5
// speedup vs baseline: 5.8868x; 3.7860x over previous
#include <cuda_runtime.h>
#include <cstdint>
#include <math.h>

#define HW 4096
#define PW 66
#define PHW 4356          // 66*66
#define HIDC 128
#define BB 4
#define OO 8
#define CC 256

#define STAGE 25600       // A: 16384 B + B: 32*72*4 = 9216 B
#define CONV_DSM (2*STAGE)

// ---------------------------------------------------------------------------
// Scratch (device globals; allocation forbidden)
// ---------------------------------------------------------------------------
__device__ float g_pst0[BB*OO*HIDC*PHW];     // padded states ping
__device__ float g_pst1[BB*OO*HIDC*PHW];     // padded states pong
__device__ float g_pS[BB*HIDC*PHW];          // padded sum-over-objects
__device__ float g_pfeats[BB*CC*PHW];        // padded feats
__device__ float g_pbase[BB*HIDC*PHW];       // padded enc base
__device__ float g_T[BB*HIDC*HW];            // unpadded shared gcn term
__device__ float g_rbase[BB*HW];
__device__ float g_wencp[HIDC*CC*9];         // fragment-packed enc weights (tf32)
__device__ float g_w2p[HIDC*HIDC*9];         // fragment-packed W2
__device__ float g_wdp[HIDC*HIDC*9];         // fragment-packed W1-W2

// ---------------------------------------------------------------------------
__device__ __forceinline__ uint32_t f2tf32(float f) {
    uint32_t r; asm("cvt.rna.tf32.f32 %0, %1;" : "=r"(r) : "f"(f)); return r;
}

__device__ __forceinline__ void mma_tf32(float* c, const uint32_t* a,
                                         uint32_t b0, uint32_t b1) {
    asm("mma.sync.aligned.m16n8k8.row.col.f32.tf32.tf32.f32 "
        "{%0,%1,%2,%3}, {%4,%5,%6,%7}, {%8,%9}, {%0,%1,%2,%3};"
        : "+f"(c[0]), "+f"(c[1]), "+f"(c[2]), "+f"(c[3])
        : "r"(a[0]), "r"(a[1]), "r"(a[2]), "r"(a[3]), "r"(b0), "r"(b1));
}

// ---------------------------------------------------------------------------
// Implicit-GEMM 3x3 conv via mma.sync tf32. Cout=128 (M), N=64 px (one row),
// K = 9*CIN tap-major. A fragment-packed in gmem; B gathered from padded input.
// Block 256 thr (8 warps: 2 M x 4 N). grid (64 rows, nImg).
// ---------------------------------------------------------------------------
__global__ void __launch_bounds__(256, 2)
conv_mma(const float* __restrict__ pin, int CIN,
         const float* __restrict__ wpack,
         const float* __restrict__ bias,
         const float* __restrict__ addend, int addDiv,
         float* __restrict__ outp, int outPadded, int doRelu)
{
    extern __shared__ __align__(16) char dsm[];
    const int tid  = threadIdx.x;
    const int lane = tid & 31, wid = tid >> 5;
    const int wm   = wid & 1,  wn  = wid >> 1;
    const int img  = blockIdx.y, row = blockIdx.x;
    const int K = CIN * 9, nchunk = K / 32;
    const float* pimg = pin + (long)img * CIN * PHW;

    float acc[4][2][4];
    #pragma unroll
    for (int mt = 0; mt < 4; mt++)
        #pragma unroll
        for (int nt = 0; nt < 2; nt++)
            #pragma unroll
            for (int e = 0; e < 4; e++) acc[mt][nt][e] = 0.f;

    uint4    ra[4];
    uint32_t rb[8];
    const int bkk = tid >> 3;       // cin-row within chunk (0..31)
    const int bpx = tid & 7;        // px phase (coalesced lane-major)

    // ---- load chunk i into registers
    auto loadChunk = [&](int i) {
        const uint4* wp = (const uint4*)(wpack + (long)i * 4096);
        #pragma unroll
        for (int j = 0; j < 4; j++) ra[j] = wp[j * 256 + tid];
        const int k0 = i * 32, tap = k0 / CIN, cbase = k0 - tap * CIN;
        const int dy = tap / 3 - 1, dx = tap % 3 - 1;
        const float* src = pimg + (long)(cbase + bkk) * PHW
                           + (row + dy + 1) * PW + (dx + 1) + bpx;
        #pragma unroll
        for (int j = 0; j < 8; j++) rb[j] = f2tf32(src[8 * j]);
    };
    // ---- store registers into stage s
    auto stsChunk = [&](int s) {
        uint4* As = (uint4*)(dsm + s * STAGE);
        #pragma unroll
        for (int j = 0; j < 4; j++) As[j * 256 + tid] = ra[j];
        uint32_t* Bs = (uint32_t*)(dsm + s * STAGE + 16384);
        #pragma unroll
        for (int j = 0; j < 8; j++) Bs[bkk * 72 + bpx + 8 * j] = rb[j];
    };
    // ---- compute on stage s
    auto compute = [&](int s) {
        const uint4*    As = (const uint4*)(dsm + s * STAGE);
        const uint32_t* Bs = (const uint32_t*)(dsm + s * STAGE + 16384);
        #pragma unroll
        for (int kt = 0; kt < 4; kt++) {
            uint4 a[4];
            #pragma unroll
            for (int mt = 0; mt < 4; mt++)
                a[mt] = As[(kt * 8 + wm * 4 + mt) * 32 + lane];
            #pragma unroll
            for (int nt = 0; nt < 2; nt++) {
                const int n = wn * 16 + nt * 8 + (lane >> 2);
                uint32_t b0 = Bs[(kt * 8 + (lane & 3)) * 72 + n];
                uint32_t b1 = Bs[(kt * 8 + (lane & 3) + 4) * 72 + n];
                #pragma unroll
                for (int mt = 0; mt < 4; mt++)
                    mma_tf32(acc[mt][nt], (const uint32_t*)&a[mt], b0, b1);
            }
        }
    };

    loadChunk(0);
    stsChunk(0);
    __syncthreads();
    for (int i = 0; i < nchunk; i++) {
        if (i + 1 < nchunk) loadChunk(i + 1);
        compute(i & 1);
        if (i + 1 < nchunk) stsChunk((i + 1) & 1);
        __syncthreads();
    }

    // ---- epilogue
    const int addImg = addDiv ? (img / addDiv) : 0;
    #pragma unroll
    for (int mt = 0; mt < 4; mt++) {
        #pragma unroll
        for (int nt = 0; nt < 2; nt++) {
            const int px = wn * 16 + nt * 8 + 2 * (lane & 3);
            #pragma unroll
            for (int h = 0; h < 2; h++) {   // h=0: rows r, h=1: rows r+8
                const int oc = wm * 64 + mt * 16 + (lane >> 2) + h * 8;
                float v0 = acc[mt][nt][2 * h + 0];
                float v1 = acc[mt][nt][2 * h + 1];
                if (bias) { float bv = bias[oc]; v0 += bv; v1 += bv; }
                if (addend) {
                    const float2 ad = *(const float2*)(addend
                        + ((long)addImg * HIDC + oc) * HW + row * 64 + px);
                    v0 += ad.x; v1 += ad.y;
                }
                if (doRelu) { v0 = fmaxf(v0, 0.f); v1 = fmaxf(v1, 0.f); }
                if (outPadded) {
                    float* op = outp + ((long)img * HIDC + oc) * PHW
                                + (row + 1) * PW + 1 + px;
                    op[0] = v0; op[1] = v1;
                } else {
                    *(float2*)(outp + ((long)img * HIDC + oc) * HW
                               + row * 64 + px) = make_float2(v0, v1);
                }
            }
        }
    }
}

// ---------------------------------------------------------------------------
// Weight fragment packing. Dest index decode:
// i=chunk(32k), kt=kstep(8k), mt=mtile(16oc), lane, e(frag reg).
// a0:(r,c) a1:(r+8,c) a2:(r,c+4) a3:(r+8,c+4); r=lane>>2, c=lane&3.
// K index is tap-major: k = tap*CIN + cin.
// ---------------------------------------------------------------------------
__global__ void prep_enc_pack(const float* __restrict__ ew, float* __restrict__ wp) {
    int idx = blockIdx.x * 256 + threadIdx.x;
    if (idx >= HIDC * CC * 9) return;
    int i = idx >> 12, rem = idx & 4095;
    int kt = rem >> 10, r2 = rem & 1023;
    int mt = r2 >> 7, r3 = r2 & 127;
    int lane = r3 >> 2, e = r3 & 3;
    int oc = mt * 16 + (lane >> 2) + ((e & 1) << 3);
    int k  = i * 32 + kt * 8 + (lane & 3) + ((e >> 1) << 2);
    int tap = k / CC, cin = k % CC;
    wp[idx] = __uint_as_float(f2tf32(ew[((long)oc * 257 + cin) * 9 + tap]));
}
__global__ void prep_gcn_pack(const float* __restrict__ gw,
                              float* __restrict__ w2p, float* __restrict__ wdp) {
    int idx = blockIdx.x * 256 + threadIdx.x;
    if (idx >= HIDC * HIDC * 9) return;
    int i = idx >> 12, rem = idx & 4095;
    int kt = rem >> 10, r2 = rem & 1023;
    int mt = r2 >> 7, r3 = r2 & 127;
    int lane = r3 >> 2, e = r3 & 3;
    int oc = mt * 16 + (lane >> 2) + ((e & 1) << 3);
    int k  = i * 32 + kt * 8 + (lane & 3) + ((e >> 1) << 2);
    int tap = k / HIDC, cin = k % HIDC;
    float a = gw[((long)oc * 2 * HIDC + cin) * 9 + tap];
    float b = gw[((long)oc * 2 * HIDC + HIDC + cin) * 9 + tap];
    w2p[idx] = __uint_as_float(f2tf32(b));
    wdp[idx] = __uint_as_float(f2tf32(a - b));
}

// ---------------------------------------------------------------------------
// Pad / small kernels
// ---------------------------------------------------------------------------
__global__ void pad_feats_k(const float* __restrict__ f, float* __restrict__ pf) {
    long idx = (long)blockIdx.x * 256 + threadIdx.x;
    if (idx >= (long)BB * CC * PHW) return;
    long ch = idx / PHW; int p = (int)(idx % PHW); int y = p / PW, x = p % PW;
    float v = 0.f;
    if (y >= 1 && y <= 64 && x >= 1 && x <= 64)
        v = f[ch * HW + (y - 1) * 64 + (x - 1)];
    pf[idx] = v;
}
__global__ void border_zero_k(float* a, float* b) {
    int idx = blockIdx.x * 256 + threadIdx.x;
    const int CH = BB * OO * HIDC;
    if (idx >= 2 * CH * 260) return;
    float* arr = (idx < CH * 260) ? a : b;
    int r = idx % (CH * 260);
    int ch = r / 260, p = r % 260, y, x;
    if (p < 66)       { y = 0;           x = p; }
    else if (p < 132) { y = 65;          x = p - 66; }
    else if (p < 196) { y = p - 132 + 1; x = 0; }
    else              { y = p - 196 + 1; x = 65; }
    arr[(long)ch * PHW + y * PW + x] = 0.f;
}
__global__ void sumO_k(const float* __restrict__ st, float* __restrict__ S) {
    long idx = (long)blockIdx.x * 256 + threadIdx.x;
    if (idx >= (long)BB * HIDC * PHW) return;
    int b = (int)(idx / (HIDC * PHW));
    long r = idx - (long)b * HIDC * PHW;
    const float* p = st + (long)b * OO * HIDC * PHW + r;
    float s = 0.f;
    #pragma unroll
    for (int o = 0; o < OO; o++) s += p[(long)o * HIDC * PHW];
    S[idx] = s;
}
// enc per-object: states = relu(base + conv3x3(mask, enc_w[:,256]))  (padded io)
__global__ void __launch_bounds__(256) enc_obj_k(
    const float* __restrict__ masks, const float* __restrict__ enc_w,
    const float* __restrict__ pbase, float* __restrict__ pst)
{
    __shared__ float wm[HIDC * 9];
    const int tid = threadIdx.x;
    const int img = blockIdx.y;
    const int p   = blockIdx.x * 256 + tid;
    for (int t = tid; t < HIDC * 9; t += 256) {
        int oc = t / 9, k = t - oc * 9;
        wm[t] = enc_w[((long)oc * 257 + 256) * 9 + k];
    }
    __syncthreads();
    const int y = p >> 6, x = p & 63;
    float m[3][3];
    #pragma unroll
    for (int i = 0; i < 3; i++)
        #pragma unroll
        for (int j = 0; j < 3; j++) {
            int gy = y - 1 + i, gx = x - 1 + j;
            m[i][j] = ((unsigned)gy < 64u && (unsigned)gx < 64u)
                        ? masks[(long)img * HW + gy * 64 + gx] : 0.f;
        }
    const int b = img >> 3;
    const int pp = (y + 1) * PW + x + 1;
    const float* bimg = pbase + (long)b * HIDC * PHW;
    float* simg = pst + (long)img * HIDC * PHW;
    #pragma unroll 4
    for (int oc = 0; oc < HIDC; oc++) {
        float a = bimg[oc * PHW + pp];
        #pragma unroll
        for (int k = 0; k < 9; k++) a = fmaf(wm[oc * 9 + k], m[k / 3][k % 3], a);
        simg[oc * PHW + pp] = fmaxf(a, 0.f);
    }
}
// readout base: rbase[b,p] = ro_b + conv3x3(feats_b, ro_w[:, :256]) (unpadded feats)
__global__ void __launch_bounds__(256) ro_base_k(
    const float* __restrict__ feats, const float* __restrict__ ro_w,
    const float* __restrict__ ro_b, float* __restrict__ rbase)
{
    __shared__ float tile[18 * 18];
    __shared__ float ws[CC * 9];
    const int tid = threadIdx.x;
    const int img = blockIdx.y;
    const int tx0 = (blockIdx.x & 3) * 16, ty0 = (blockIdx.x >> 2) * 16;
    for (int t = tid; t < CC * 9; t += 256) ws[t] = ro_w[t];
    const int px = tid & 15, py = tid >> 4;
    float acc = ro_b[0];
    const float* fimg = feats + (long)img * CC * HW;
    for (int ic = 0; ic < CC; ic++) {
        __syncthreads();
        for (int t = tid; t < 18 * 18; t += 256) {
            int yy = t / 18, xx = t - yy * 18;
            int gy = ty0 - 1 + yy, gx = tx0 - 1 + xx;
            tile[t] = ((unsigned)gy < 64u && (unsigned)gx < 64u)
                        ? fimg[(long)ic * HW + gy * 64 + gx] : 0.f;
        }
        __syncthreads();
        #pragma unroll
        for (int k = 0; k < 9; k++)
            acc = fmaf(ws[ic * 9 + k], tile[(py + k / 3) * 18 + px + (k % 3)], acc);
    }
    rbase[(long)img * HW + (ty0 + py) * 64 + tx0 + px] = acc;
}
// readout per-object (padded states in)
__global__ void __launch_bounds__(256) ro_obj_k(
    const float* __restrict__ pst, const float* __restrict__ ro_w,
    const float* __restrict__ rbase, float* __restrict__ outp)
{
    __shared__ float tile[18 * 18];
    __shared__ float ws[HIDC * 9];
    const int tid = threadIdx.x;
    const int img = blockIdx.y;
    const int tx0 = (blockIdx.x & 3) * 16, ty0 = (blockIdx.x >> 2) * 16;
    for (int t = tid; t < HIDC * 9; t += 256) ws[t] = ro_w[(long)CC * 9 + t];
    const int px = tid & 15, py = tid >> 4;
    float acc = 0.f;
    const float* simg = pst + (long)img * HIDC * PHW;
    for (int ic = 0; ic < HIDC; ic++) {
        __syncthreads();
        for (int t = tid; t < 18 * 18; t += 256) {
            int yy = t / 18, xx = t - yy * 18;
            tile[t] = simg[(long)ic * PHW + (ty0 + yy) * PW + tx0 + xx];
        }
        __syncthreads();
        #pragma unroll
        for (int k = 0; k < 9; k++)
            acc = fmaf(ws[ic * 9 + k], tile[(py + k / 3) * 18 + px + (k % 3)], acc);
    }
    const int b = img >> 3;
    float z = acc + rbase[(long)b * HW + (ty0 + py) * 64 + tx0 + px];
    outp[(long)img * HW + (ty0 + py) * 64 + tx0 + px] = 1.f / (1.f + expf(-z));
}

// ---------------------------------------------------------------------------
extern "C" void kernel_launch(void* const* d_in, const int* in_sizes, int n_in,
                              void* d_out, int out_size)
{
    const float* feats = (const float*)d_in[0];
    const float* masks = (const float*)d_in[1];
    const float* enc_w = (const float*)d_in[4];
    const float* enc_b = (const float*)d_in[5];
    const float* gcn_w = (const float*)d_in[6];
    const float* gcn_b = (const float*)d_in[7];
    const float* ro_w  = (const float*)d_in[8];
    const float* ro_b  = (const float*)d_in[9];
    float* outp = (float*)d_out;

    float *pst0, *pst1, *pS, *pfeats, *pbase, *T, *rbase, *wencp, *w2p, *wdp;
    cudaGetSymbolAddress((void**)&pst0,   g_pst0);
    cudaGetSymbolAddress((void**)&pst1,   g_pst1);
    cudaGetSymbolAddress((void**)&pS,     g_pS);
    cudaGetSymbolAddress((void**)&pfeats, g_pfeats);
    cudaGetSymbolAddress((void**)&pbase,  g_pbase);
    cudaGetSymbolAddress((void**)&T,      g_T);
    cudaGetSymbolAddress((void**)&rbase,  g_rbase);
    cudaGetSymbolAddress((void**)&wencp,  g_wencp);
    cudaGetSymbolAddress((void**)&w2p,    g_w2p);
    cudaGetSymbolAddress((void**)&wdp,    g_wdp);

    cudaFuncSetAttribute(conv_mma, cudaFuncAttributeMaxDynamicSharedMemorySize,
                         CONV_DSM);

    prep_enc_pack<<<(HIDC*CC*9 + 255)/256, 256>>>(enc_w, wencp);
    prep_gcn_pack<<<(HIDC*HIDC*9 + 255)/256, 256>>>(gcn_w, w2p, wdp);
    pad_feats_k<<<(int)(((long)BB*CC*PHW + 255)/256), 256>>>(feats, pfeats);
    border_zero_k<<<(2*BB*OO*HIDC*260 + 255)/256, 256>>>(pst0, pst1);

    // enc base: conv(pfeats, enc_w[:, :256]) + enc_b -> padded base
    conv_mma<<<dim3(64, BB), 256, CONV_DSM>>>(pfeats, CC, wencp, enc_b,
                                              nullptr, 0, pbase, 1, 0);
    // enc per-object
    enc_obj_k<<<dim3(16, BB*OO), 256>>>(masks, enc_w, pbase, pst0);

    float* cur = pst0; float* nxt = pst1;
    for (int s = 0; s < 2; s++) {
        sumO_k<<<(int)(((long)BB*HIDC*PHW + 255)/256), 256>>>(cur, pS);
        // T = conv(S, W2) + gcn_b (unpadded out)
        conv_mma<<<dim3(64, BB), 256, CONV_DSM>>>(pS, HIDC, w2p, gcn_b,
                                                  nullptr, 0, T, 0, 0);
        // states' = relu(conv(states, Wd) + T) (padded out)
        conv_mma<<<dim3(64, BB*OO), 256, CONV_DSM>>>(cur, HIDC, wdp, nullptr,
                                                     T, OO, nxt, 1, 1);
        float* tmp = cur; cur = nxt; nxt = tmp;
    }

    ro_base_k<<<dim3(16, BB), 256>>>(feats, ro_w, ro_b, rbase);
    ro_obj_k<<<dim3(16, BB*OO), 256>>>(cur, ro_w, rbase, outp);
}

// round 6
// speedup vs baseline: 9.1733x; 1.5583x over previous
#include <cuda_runtime.h>
#include <cstdint>
#include <math.h>

#define HW 4096
#define PW 68
#define PHW 4624          // 68*68, rows 16B-aligned
#define HIDC 128
#define BB 4
#define OO 8
#define CC 256

#define STAGE 33792       // A 16384 + B 32*136*4 = 17408
#define CONV_DSM (3*STAGE)

// ---------------------------------------------------------------------------
// Scratch (device globals; allocation forbidden). Zero-initialized at load;
// borders of padded buffers are NEVER written -> stay zero across replays.
// ---------------------------------------------------------------------------
__device__ float g_pst0[BB*OO*HIDC*PHW];     // padded states ping (tf32-rounded)
__device__ float g_pst1[BB*OO*HIDC*PHW];     // padded states pong
__device__ float g_pS[BB*HIDC*PHW];          // padded sum-over-objects (rounded)
__device__ float g_pfeats[BB*CC*PHW];        // padded feats (rounded)
__device__ float g_pbase[BB*HIDC*PHW];       // padded enc base (full fp32)
__device__ float g_T[BB*HIDC*HW];            // unpadded shared gcn term (fp32)
__device__ float g_rpart[4*BB*HW];           // readout base partials (4 cin slices)
__device__ float g_wencp[HIDC*CC*9];         // fragment-packed enc weights (tf32)
__device__ float g_w2p[HIDC*HIDC*9];         // fragment-packed W2
__device__ float g_wdp[HIDC*HIDC*9];         // fragment-packed W1-W2

// ---------------------------------------------------------------------------
__device__ __forceinline__ uint32_t f2tf32(float f) {
    uint32_t r; asm("cvt.rna.tf32.f32 %0, %1;" : "=r"(r) : "f"(f)); return r;
}
__device__ __forceinline__ float roundtf(float f) {
    return __uint_as_float(f2tf32(f));
}
#define CP16(dst, src) \
    asm volatile("cp.async.cg.shared.global [%0], [%1], 16;" \
                 :: "r"(dst), "l"(src) : "memory")

__device__ __forceinline__ void mma_tf32(float* c, const uint32_t* a,
                                         uint32_t b0, uint32_t b1) {
    asm("mma.sync.aligned.m16n8k8.row.col.f32.tf32.tf32.f32 "
        "{%0,%1,%2,%3}, {%4,%5,%6,%7}, {%8,%9}, {%0,%1,%2,%3};"
        : "+f"(c[0]), "+f"(c[1]), "+f"(c[2]), "+f"(c[3])
        : "r"(a[0]), "r"(a[1]), "r"(a[2]), "r"(a[3]), "r"(b0), "r"(b1));
}

// ---------------------------------------------------------------------------
// Implicit-GEMM 3x3 conv via mma.sync tf32, cp.async 3-stage pipeline.
// M=128 oc, N=128 px (2 image rows), K=9*CIN tap-major (32-k chunks, 1 tap each).
// A fragment-packed in gmem (pure 16B copy). B: 32 cin x 2 rows x 68 floats
// (full padded rows, 16B-aligned); tap dx applied at smem read offset.
// Block 256 thr (8 warps: 2 M x 4 N). grid (32 row-pairs, nImg).
// ---------------------------------------------------------------------------
template<int CIN>
__global__ void __launch_bounds__(256, 2)
conv_mma(const float* __restrict__ pin,
         const float* __restrict__ wpack,
         const float* __restrict__ bias,
         const float* __restrict__ addend, int addDiv,
         float* __restrict__ outp, int outPadded, int doRelu, int roundOut)
{
    extern __shared__ __align__(16) char dsm[];
    const int tid  = threadIdx.x;
    const int lane = tid & 31, wid = tid >> 5;
    const int wm   = wid & 1,  wn  = wid >> 1;
    const int img  = blockIdx.y, row0 = blockIdx.x * 2;
    constexpr int CPT = CIN / 32;         // chunks per tap
    constexpr int nchunk = CPT * 9;
    const float* pimg = pin + (long)img * CIN * PHW;
    const uint32_t smbase = (uint32_t)__cvta_generic_to_shared(dsm);

    float acc[4][4][4];
    #pragma unroll
    for (int mt = 0; mt < 4; mt++)
        #pragma unroll
        for (int nt = 0; nt < 4; nt++)
            #pragma unroll
            for (int e = 0; e < 4; e++) acc[mt][nt][e] = 0.f;

    auto issueChunk = [&](int i) {
        const int st = i % 3;
        const uint32_t abase = smbase + st * STAGE;
        const uint32_t bbase = abase + 16384;
        const float* asrc = wpack + (long)i * 4096;
        #pragma unroll
        for (int j = 0; j < 4; j++) {
            const int u = tid + j * 256;
            CP16(abase + u * 16, asrc + u * 4);
        }
        const int tap = i / CPT, cbase = (i - tap * CPT) * 32;
        const int y0 = row0 + (tap / 3 - 1) + 1;   // 0..65
        #pragma unroll
        for (int v = 0; v < 5; v++) {
            const int o = tid + v * 256;
            if (o < 1088) {
                const int cin = o / 34, rem = o - cin * 34;
                const int j = rem / 17, q = rem - j * 17;
                const float* src = pimg + (long)(cbase + cin) * PHW
                                   + (y0 + j) * PW + q * 4;
                const uint32_t dst = bbase + (cin * 136 + j * 68 + q * 4) * 4;
                CP16(dst, src);
            }
        }
        asm volatile("cp.async.commit_group;" ::: "memory");
    };

    auto compute = [&](int s, int dx) {
        const uint4*  As = (const uint4*)(dsm + s * STAGE);
        const float*  Bs = (const float*)(dsm + s * STAGE + 16384);
        #pragma unroll
        for (int kt = 0; kt < 4; kt++) {
            uint4 a[4];
            #pragma unroll
            for (int mt = 0; mt < 4; mt++)
                a[mt] = As[(kt * 8 + wm * 4 + mt) * 32 + lane];
            #pragma unroll
            for (int nt = 0; nt < 4; nt++) {
                const int n   = wn * 32 + nt * 8 + (lane >> 2);
                const int col = (n >> 6) * 68 + (n & 63) + 1 + dx;
                const float* bp = Bs + (kt * 8 + (lane & 3)) * 136 + col;
                const uint32_t b0 = __float_as_uint(bp[0]);
                const uint32_t b1 = __float_as_uint(bp[4 * 136]);
                #pragma unroll
                for (int mt = 0; mt < 4; mt++)
                    mma_tf32(acc[mt][nt], (const uint32_t*)&a[mt], b0, b1);
            }
        }
    };

    issueChunk(0); issueChunk(1); issueChunk(2);
    for (int i = 0; i < nchunk; i++) {
        asm volatile("cp.async.wait_group 2;" ::: "memory");
        __syncthreads();
        const int dx = (i / CPT) % 3 - 1;
        compute(i % 3, dx);
        __syncthreads();
        if (i + 3 < nchunk) issueChunk(i + 3);
        else asm volatile("cp.async.commit_group;" ::: "memory");
    }

    // ---- epilogue
    const int addImg = addDiv ? (img / addDiv) : 0;
    #pragma unroll
    for (int mt = 0; mt < 4; mt++) {
        #pragma unroll
        for (int h = 0; h < 2; h++) {
            const int oc = wm * 64 + mt * 16 + (lane >> 2) + h * 8;
            const float bv = bias ? bias[oc] : 0.f;
            #pragma unroll
            for (int nt = 0; nt < 4; nt++) {
                const int n = wn * 32 + nt * 8 + 2 * (lane & 3);
                const int r = n >> 6, x = n & 63;
                float v0 = acc[mt][nt][2 * h + 0] + bv;
                float v1 = acc[mt][nt][2 * h + 1] + bv;
                if (addend) {
                    const float2 ad = *(const float2*)(addend
                        + ((long)addImg * HIDC + oc) * HW + (row0 + r) * 64 + x);
                    v0 += ad.x; v1 += ad.y;
                }
                if (doRelu) { v0 = fmaxf(v0, 0.f); v1 = fmaxf(v1, 0.f); }
                if (roundOut) { v0 = roundtf(v0); v1 = roundtf(v1); }
                if (outPadded) {
                    float* op = outp + ((long)img * HIDC + oc) * PHW
                                + (row0 + r + 1) * PW + 1 + x;
                    op[0] = v0; op[1] = v1;
                } else {
                    *(float2*)(outp + ((long)img * HIDC + oc) * HW
                               + (row0 + r) * 64 + x) = make_float2(v0, v1);
                }
            }
        }
    }
}

// ---------------------------------------------------------------------------
// Weight fragment packing (same layout as R5; chunk stride 4096 floats).
// ---------------------------------------------------------------------------
__global__ void prep_enc_pack(const float* __restrict__ ew, float* __restrict__ wp) {
    int idx = blockIdx.x * 256 + threadIdx.x;
    if (idx >= HIDC * CC * 9) return;
    int i = idx >> 12, rem = idx & 4095;
    int kt = rem >> 10, r2 = rem & 1023;
    int mt = r2 >> 7, r3 = r2 & 127;
    int lane = r3 >> 2, e = r3 & 3;
    int oc = mt * 16 + (lane >> 2) + ((e & 1) << 3);
    int k  = i * 32 + kt * 8 + (lane & 3) + ((e >> 1) << 2);
    int tap = k / CC, cin = k % CC;
    wp[idx] = __uint_as_float(f2tf32(ew[((long)oc * 257 + cin) * 9 + tap]));
}
__global__ void prep_gcn_pack(const float* __restrict__ gw,
                              float* __restrict__ w2p, float* __restrict__ wdp) {
    int idx = blockIdx.x * 256 + threadIdx.x;
    if (idx >= HIDC * HIDC * 9) return;
    int i = idx >> 12, rem = idx & 4095;
    int kt = rem >> 10, r2 = rem & 1023;
    int mt = r2 >> 7, r3 = r2 & 127;
    int lane = r3 >> 2, e = r3 & 3;
    int oc = mt * 16 + (lane >> 2) + ((e & 1) << 3);
    int k  = i * 32 + kt * 8 + (lane & 3) + ((e >> 1) << 2);
    int tap = k / HIDC, cin = k % HIDC;
    float a = gw[((long)oc * 2 * HIDC + cin) * 9 + tap];
    float b = gw[((long)oc * 2 * HIDC + HIDC + cin) * 9 + tap];
    w2p[idx] = __uint_as_float(f2tf32(b));
    wdp[idx] = __uint_as_float(f2tf32(a - b));
}

// ---------------------------------------------------------------------------
// Pad / small kernels
// ---------------------------------------------------------------------------
__global__ void pad_feats_k(const float* __restrict__ f, float* __restrict__ pf) {
    long idx = (long)blockIdx.x * 256 + threadIdx.x;
    if (idx >= (long)BB * CC * PHW) return;
    long ch = idx / PHW; int p = (int)(idx % PHW); int y = p / PW, x = p % PW;
    float v = 0.f;
    if (y >= 1 && y <= 64 && x >= 1 && x <= 64)
        v = roundtf(f[ch * HW + (y - 1) * 64 + (x - 1)]);
    pf[idx] = v;
}
__global__ void sumO_k(const float* __restrict__ st, float* __restrict__ S) {
    long idx = (long)blockIdx.x * 256 + threadIdx.x;
    if (idx >= (long)BB * HIDC * PHW) return;
    int b = (int)(idx / (HIDC * PHW));
    long r = idx - (long)b * HIDC * PHW;
    const float* p = st + (long)b * OO * HIDC * PHW + r;
    float s = 0.f;
    #pragma unroll
    for (int o = 0; o < OO; o++) s += p[(long)o * HIDC * PHW];
    S[idx] = roundtf(s);
}
// enc per-object: states = round(relu(base + conv3x3(mask, enc_w[:,256])))
__global__ void __launch_bounds__(256) enc_obj_k(
    const float* __restrict__ masks, const float* __restrict__ enc_w,
    const float* __restrict__ pbase, float* __restrict__ pst)
{
    __shared__ float wm[HIDC * 9];
    const int tid = threadIdx.x;
    const int img = blockIdx.y;
    const int p   = blockIdx.x * 256 + tid;
    for (int t = tid; t < HIDC * 9; t += 256) {
        int oc = t / 9, k = t - oc * 9;
        wm[t] = enc_w[((long)oc * 257 + 256) * 9 + k];
    }
    __syncthreads();
    const int y = p >> 6, x = p & 63;
    float m[3][3];
    #pragma unroll
    for (int i = 0; i < 3; i++)
        #pragma unroll
        for (int j = 0; j < 3; j++) {
            int gy = y - 1 + i, gx = x - 1 + j;
            m[i][j] = ((unsigned)gy < 64u && (unsigned)gx < 64u)
                        ? masks[(long)img * HW + gy * 64 + gx] : 0.f;
        }
    const int b = img >> 3;
    const int pp = (y + 1) * PW + x + 1;
    const float* bimg = pbase + (long)b * HIDC * PHW;
    float* simg = pst + (long)img * HIDC * PHW;
    #pragma unroll 4
    for (int oc = 0; oc < HIDC; oc++) {
        float a = bimg[oc * PHW + pp];
        #pragma unroll
        for (int k = 0; k < 9; k++) a = fmaf(wm[oc * 9 + k], m[k / 3][k % 3], a);
        simg[oc * PHW + pp] = roundtf(fmaxf(a, 0.f));
    }
}
// readout base partials: rpart[slice][b] = (slice==0 ? ro_b : 0) +
//   conv3x3(feats[slice*64 .. +63], ro_w slice). grid (16, BB, 4)
__global__ void __launch_bounds__(256) ro_base_k(
    const float* __restrict__ feats, const float* __restrict__ ro_w,
    const float* __restrict__ ro_b, float* __restrict__ rpart)
{
    __shared__ float tile[18 * 18];
    __shared__ float ws[64 * 9];
    const int tid = threadIdx.x;
    const int img = blockIdx.y;
    const int sl  = blockIdx.z;
    const int tx0 = (blockIdx.x & 3) * 16, ty0 = (blockIdx.x >> 2) * 16;
    for (int t = tid; t < 64 * 9; t += 256) ws[t] = ro_w[sl * 64 * 9 + t];
    const int px = tid & 15, py = tid >> 4;
    float acc = (sl == 0) ? ro_b[0] : 0.f;
    const float* fimg = feats + ((long)img * CC + sl * 64) * HW;
    for (int ic = 0; ic < 64; ic++) {
        __syncthreads();
        for (int t = tid; t < 18 * 18; t += 256) {
            int yy = t / 18, xx = t - yy * 18;
            int gy = ty0 - 1 + yy, gx = tx0 - 1 + xx;
            tile[t] = ((unsigned)gy < 64u && (unsigned)gx < 64u)
                        ? fimg[(long)ic * HW + gy * 64 + gx] : 0.f;
        }
        __syncthreads();
        #pragma unroll
        for (int k = 0; k < 9; k++)
            acc = fmaf(ws[ic * 9 + k], tile[(py + k / 3) * 18 + px + (k % 3)], acc);
    }
    rpart[((long)sl * BB + img) * HW + (ty0 + py) * 64 + tx0 + px] = acc;
}
// readout per-object (padded, unrounded final states in)
__global__ void __launch_bounds__(256) ro_obj_k(
    const float* __restrict__ pst, const float* __restrict__ ro_w,
    const float* __restrict__ rpart, float* __restrict__ outp)
{
    __shared__ float tile[18 * 18];
    __shared__ float ws[HIDC * 9];
    const int tid = threadIdx.x;
    const int img = blockIdx.y;
    const int tx0 = (blockIdx.x & 3) * 16, ty0 = (blockIdx.x >> 2) * 16;
    for (int t = tid; t < HIDC * 9; t += 256) ws[t] = ro_w[(long)CC * 9 + t];
    const int px = tid & 15, py = tid >> 4;
    float acc = 0.f;
    const float* simg = pst + (long)img * HIDC * PHW;
    for (int ic = 0; ic < HIDC; ic++) {
        __syncthreads();
        for (int t = tid; t < 18 * 18; t += 256) {
            int yy = t / 18, xx = t - yy * 18;
            tile[t] = simg[(long)ic * PHW + (ty0 + yy) * PW + tx0 + xx];
        }
        __syncthreads();
        #pragma unroll
        for (int k = 0; k < 9; k++)
            acc = fmaf(ws[ic * 9 + k], tile[(py + k / 3) * 18 + px + (k % 3)], acc);
    }
    const int b = img >> 3;
    const long po = (long)b * HW + (ty0 + py) * 64 + tx0 + px;
    float z = acc + rpart[po] + rpart[(long)BB * HW + po]
              + rpart[2L * BB * HW + po] + rpart[3L * BB * HW + po];
    outp[(long)img * HW + (ty0 + py) * 64 + tx0 + px] = 1.f / (1.f + expf(-z));
}

// ---------------------------------------------------------------------------
extern "C" void kernel_launch(void* const* d_in, const int* in_sizes, int n_in,
                              void* d_out, int out_size)
{
    const float* feats = (const float*)d_in[0];
    const float* masks = (const float*)d_in[1];
    const float* enc_w = (const float*)d_in[4];
    const float* enc_b = (const float*)d_in[5];
    const float* gcn_w = (const float*)d_in[6];
    const float* gcn_b = (const float*)d_in[7];
    const float* ro_w  = (const float*)d_in[8];
    const float* ro_b  = (const float*)d_in[9];
    float* outp = (float*)d_out;

    float *pst0, *pst1, *pS, *pfeats, *pbase, *T, *rpart, *wencp, *w2p, *wdp;
    cudaGetSymbolAddress((void**)&pst0,   g_pst0);
    cudaGetSymbolAddress((void**)&pst1,   g_pst1);
    cudaGetSymbolAddress((void**)&pS,     g_pS);
    cudaGetSymbolAddress((void**)&pfeats, g_pfeats);
    cudaGetSymbolAddress((void**)&pbase,  g_pbase);
    cudaGetSymbolAddress((void**)&T,      g_T);
    cudaGetSymbolAddress((void**)&rpart,  g_rpart);
    cudaGetSymbolAddress((void**)&wencp,  g_wencp);
    cudaGetSymbolAddress((void**)&w2p,    g_w2p);
    cudaGetSymbolAddress((void**)&wdp,    g_wdp);

    cudaFuncSetAttribute(conv_mma<128>,
                         cudaFuncAttributeMaxDynamicSharedMemorySize, CONV_DSM);
    cudaFuncSetAttribute(conv_mma<256>,
                         cudaFuncAttributeMaxDynamicSharedMemorySize, CONV_DSM);

    prep_enc_pack<<<(HIDC*CC*9 + 255)/256, 256>>>(enc_w, wencp);
    prep_gcn_pack<<<(HIDC*HIDC*9 + 255)/256, 256>>>(gcn_w, w2p, wdp);
    pad_feats_k<<<(int)(((long)BB*CC*PHW + 255)/256), 256>>>(feats, pfeats);

    // enc base: conv(pfeats, enc_w[:, :256]) + enc_b -> padded base (fp32)
    conv_mma<256><<<dim3(32, BB), 256, CONV_DSM>>>(pfeats, wencp, enc_b,
                                                   nullptr, 0, pbase, 1, 0, 0);
    // enc per-object (stores rounded states)
    enc_obj_k<<<dim3(16, BB*OO), 256>>>(masks, enc_w, pbase, pst0);

    float* cur = pst0; float* nxt = pst1;
    for (int s = 0; s < 2; s++) {
        sumO_k<<<(int)(((long)BB*HIDC*PHW + 255)/256), 256>>>(cur, pS);
        // T = conv(S, W2) + gcn_b (unpadded fp32 out)
        conv_mma<128><<<dim3(32, BB), 256, CONV_DSM>>>(pS, w2p, gcn_b,
                                                       nullptr, 0, T, 0, 0, 0);
        // states' = relu(conv(states, Wd) + T); round unless final step
        conv_mma<128><<<dim3(32, BB*OO), 256, CONV_DSM>>>(cur, wdp, nullptr,
                                                          T, OO, nxt, 1, 1,
                                                          s == 0 ? 1 : 0);
        float* tmp = cur; cur = nxt; nxt = tmp;
    }

    ro_base_k<<<dim3(16, BB, 4), 256>>>(feats, ro_w, ro_b, rpart);
    ro_obj_k<<<dim3(16, BB*OO), 256>>>(cur, ro_w, rpart, outp);
}

// round 7
// speedup vs baseline: 9.5643x; 1.0426x over previous
#include <cuda_runtime.h>
#include <cstdint>
#include <math.h>

#define HW 4096
#define PW 68
#define PHW 4624          // 68*68, rows 16B-aligned
#define HIDC 128
#define BB 4
#define OO 8
#define CC 256

// 4-stage pipeline, K-chunk = 16: A 128*16*4 = 8192 B, B 16*136*4 = 8704 B
#define STAGE 16896
#define CONV_DSM (4*STAGE)

// ---------------------------------------------------------------------------
// Scratch (device globals; allocation forbidden). Zero-initialized at load;
// borders of padded buffers are NEVER written -> stay zero across replays.
// ---------------------------------------------------------------------------
__device__ float g_pst0[BB*OO*HIDC*PHW];     // padded states ping (tf32-rounded)
__device__ float g_pst1[BB*OO*HIDC*PHW];     // padded states pong
__device__ float g_pS[BB*HIDC*PHW];          // padded sum-over-objects (rounded)
__device__ float g_pfeats[BB*CC*PHW];        // padded feats (rounded)
__device__ float g_pbase[BB*HIDC*PHW];       // padded enc base (full fp32)
__device__ float g_T[BB*HIDC*HW];            // unpadded shared gcn term (fp32)
__device__ float g_rpart[4*BB*HW];           // readout base partials (4 cin slices)
__device__ float g_wencp[HIDC*CC*9];         // fragment-packed enc weights (tf32)
__device__ float g_w2p[HIDC*HIDC*9];         // fragment-packed W2
__device__ float g_wdp[HIDC*HIDC*9];         // fragment-packed W1-W2

// ---------------------------------------------------------------------------
__device__ __forceinline__ uint32_t f2tf32(float f) {
    uint32_t r; asm("cvt.rna.tf32.f32 %0, %1;" : "=r"(r) : "f"(f)); return r;
}
__device__ __forceinline__ float roundtf(float f) {
    return __uint_as_float(f2tf32(f));
}
#define CP16(dst, src) \
    asm volatile("cp.async.cg.shared.global [%0], [%1], 16;" \
                 :: "r"(dst), "l"(src) : "memory")

__device__ __forceinline__ void mma_tf32(float* c, const uint32_t* a,
                                         uint32_t b0, uint32_t b1) {
    asm("mma.sync.aligned.m16n8k8.row.col.f32.tf32.tf32.f32 "
        "{%0,%1,%2,%3}, {%4,%5,%6,%7}, {%8,%9}, {%0,%1,%2,%3};"
        : "+f"(c[0]), "+f"(c[1]), "+f"(c[2]), "+f"(c[3])
        : "r"(a[0]), "r"(a[1]), "r"(a[2]), "r"(a[3]), "r"(b0), "r"(b1));
}

// ---------------------------------------------------------------------------
// Implicit-GEMM 3x3 conv via mma.sync tf32, 4-stage cp.async pipeline,
// single __syncthreads per chunk (issue happens BEFORE compute; the stage
// overwritten by issue(i+3) was computed at i-1, protected by the barrier).
// M=128 oc, N=128 px (2 image rows), K=9*CIN tap-major, 16-k chunks (1 tap).
// Block 256 thr (8 warps: 2 M x 4 N). grid (32 row-pairs, nImg). 2 CTA/SM.
// ---------------------------------------------------------------------------
template<int CIN>
__global__ void __launch_bounds__(256, 2)
conv_mma(const float* __restrict__ pin,
         const float* __restrict__ wpack,
         const float* __restrict__ bias,
         const float* __restrict__ addend, int addDiv,
         float* __restrict__ outp, int outPadded, int doRelu, int roundOut)
{
    extern __shared__ __align__(16) char dsm[];
    const int tid  = threadIdx.x;
    const int lane = tid & 31, wid = tid >> 5;
    const int wm   = wid & 1,  wn  = wid >> 1;
    const int img  = blockIdx.y, row0 = blockIdx.x * 2;
    constexpr int CPT = CIN / 16;         // chunks per tap
    constexpr int nchunk = CPT * 9;
    const float* pimg = pin + (long)img * CIN * PHW;
    const uint32_t smbase = (uint32_t)__cvta_generic_to_shared(dsm);

    float acc[4][4][4];
    #pragma unroll
    for (int mt = 0; mt < 4; mt++)
        #pragma unroll
        for (int nt = 0; nt < 4; nt++)
            #pragma unroll
            for (int e = 0; e < 4; e++) acc[mt][nt][e] = 0.f;

    auto issueChunk = [&](int i) {
        const int st = i & 3;
        const uint32_t abase = smbase + st * STAGE;
        const uint32_t bbase = abase + 8192;
        const float* asrc = wpack + (long)i * 2048;
        #pragma unroll
        for (int j = 0; j < 2; j++) {
            const int u = tid + j * 256;
            CP16(abase + u * 16, asrc + u * 4);
        }
        const int tap = i / CPT, cbase = (i - tap * CPT) * 16;
        const int y0 = row0 + (tap / 3 - 1) + 1;   // 0..65
        #pragma unroll
        for (int v = 0; v < 3; v++) {
            const int o = tid + v * 256;
            if (o < 544) {
                const int cin = o / 34, rem = o - cin * 34;
                const int j = rem / 17, q = rem - j * 17;
                const float* src = pimg + (long)(cbase + cin) * PHW
                                   + (y0 + j) * PW + q * 4;
                const uint32_t dst = bbase + (cin * 136 + j * 68 + q * 4) * 4;
                CP16(dst, src);
            }
        }
        asm volatile("cp.async.commit_group;" ::: "memory");
    };

    auto compute = [&](int s, int dx) {
        const uint4*  As = (const uint4*)(dsm + s * STAGE);
        const float*  Bs = (const float*)(dsm + s * STAGE + 8192);
        #pragma unroll
        for (int kt = 0; kt < 2; kt++) {
            uint4 a[4];
            #pragma unroll
            for (int mt = 0; mt < 4; mt++)
                a[mt] = As[(kt * 8 + wm * 4 + mt) * 32 + lane];
            #pragma unroll
            for (int nt = 0; nt < 4; nt++) {
                const int n   = wn * 32 + nt * 8 + (lane >> 2);
                const int col = (n >> 6) * 68 + (n & 63) + 1 + dx;
                const float* bp = Bs + (kt * 8 + (lane & 3)) * 136 + col;
                const uint32_t b0 = __float_as_uint(bp[0]);
                const uint32_t b1 = __float_as_uint(bp[4 * 136]);
                #pragma unroll
                for (int mt = 0; mt < 4; mt++)
                    mma_tf32(acc[mt][nt], (const uint32_t*)&a[mt], b0, b1);
            }
        }
    };

    issueChunk(0); issueChunk(1); issueChunk(2);
    for (int i = 0; i < nchunk; i++) {
        asm volatile("cp.async.wait_group 2;" ::: "memory");
        __syncthreads();
        if (i + 3 < nchunk) issueChunk(i + 3);
        else asm volatile("cp.async.commit_group;" ::: "memory");
        compute(i & 3, (i / CPT) % 3 - 1);
    }

    // ---- epilogue
    const int addImg = addDiv ? (img / addDiv) : 0;
    #pragma unroll
    for (int mt = 0; mt < 4; mt++) {
        #pragma unroll
        for (int h = 0; h < 2; h++) {
            const int oc = wm * 64 + mt * 16 + (lane >> 2) + h * 8;
            const float bv = bias ? bias[oc] : 0.f;
            #pragma unroll
            for (int nt = 0; nt < 4; nt++) {
                const int n = wn * 32 + nt * 8 + 2 * (lane & 3);
                const int r = n >> 6, x = n & 63;
                float v0 = acc[mt][nt][2 * h + 0] + bv;
                float v1 = acc[mt][nt][2 * h + 1] + bv;
                if (addend) {
                    const float2 ad = *(const float2*)(addend
                        + ((long)addImg * HIDC + oc) * HW + (row0 + r) * 64 + x);
                    v0 += ad.x; v1 += ad.y;
                }
                if (doRelu) { v0 = fmaxf(v0, 0.f); v1 = fmaxf(v1, 0.f); }
                if (roundOut) { v0 = roundtf(v0); v1 = roundtf(v1); }
                if (outPadded) {
                    float* op = outp + ((long)img * HIDC + oc) * PHW
                                + (row0 + r + 1) * PW + 1 + x;
                    op[0] = v0; op[1] = v1;
                } else {
                    *(float2*)(outp + ((long)img * HIDC + oc) * HW
                               + (row0 + r) * 64 + x) = make_float2(v0, v1);
                }
            }
        }
    }
}

// ---------------------------------------------------------------------------
// Weight fragment packing, 16-k chunks (2048 floats each).
// Within chunk: kt(2) x mt(4) x lane(32) x e(4).
// a0:(r,c) a1:(r+8,c) a2:(r,c+4) a3:(r+8,c+4); r=lane>>2, c=lane&3.
// ---------------------------------------------------------------------------
__global__ void prep_enc_pack(const float* __restrict__ ew, float* __restrict__ wp) {
    int idx = blockIdx.x * 256 + threadIdx.x;
    if (idx >= HIDC * CC * 9) return;
    int i = idx >> 11, rem = idx & 2047;
    int kt = rem >> 10, r2 = rem & 1023;
    int mt = r2 >> 7, r3 = r2 & 127;
    int lane = r3 >> 2, e = r3 & 3;
    int oc = mt * 16 + (lane >> 2) + ((e & 1) << 3);
    int k  = i * 16 + kt * 8 + (lane & 3) + ((e >> 1) << 2);
    int tap = k / CC, cin = k % CC;
    wp[idx] = __uint_as_float(f2tf32(ew[((long)oc * 257 + cin) * 9 + tap]));
}
__global__ void prep_gcn_pack(const float* __restrict__ gw,
                              float* __restrict__ w2p, float* __restrict__ wdp) {
    int idx = blockIdx.x * 256 + threadIdx.x;
    if (idx >= HIDC * HIDC * 9) return;
    int i = idx >> 11, rem = idx & 2047;
    int kt = rem >> 10, r2 = rem & 1023;
    int mt = r2 >> 7, r3 = r2 & 127;
    int lane = r3 >> 2, e = r3 & 3;
    int oc = mt * 16 + (lane >> 2) + ((e & 1) << 3);
    int k  = i * 16 + kt * 8 + (lane & 3) + ((e >> 1) << 2);
    int tap = k / HIDC, cin = k % HIDC;
    float a = gw[((long)oc * 2 * HIDC + cin) * 9 + tap];
    float b = gw[((long)oc * 2 * HIDC + HIDC + cin) * 9 + tap];
    w2p[idx] = __uint_as_float(f2tf32(b));
    wdp[idx] = __uint_as_float(f2tf32(a - b));
}

// ---------------------------------------------------------------------------
// Pad / small kernels
// ---------------------------------------------------------------------------
__global__ void pad_feats_k(const float* __restrict__ f, float* __restrict__ pf) {
    long idx = (long)blockIdx.x * 256 + threadIdx.x;
    if (idx >= (long)BB * CC * PHW) return;
    long ch = idx / PHW; int p = (int)(idx % PHW); int y = p / PW, x = p % PW;
    float v = 0.f;
    if (y >= 1 && y <= 64 && x >= 1 && x <= 64)
        v = roundtf(f[ch * HW + (y - 1) * 64 + (x - 1)]);
    pf[idx] = v;
}
__global__ void sumO_k(const float* __restrict__ st, float* __restrict__ S) {
    long idx = (long)blockIdx.x * 256 + threadIdx.x;
    if (idx >= (long)BB * HIDC * PHW) return;
    int b = (int)(idx / (HIDC * PHW));
    long r = idx - (long)b * HIDC * PHW;
    const float* p = st + (long)b * OO * HIDC * PHW + r;
    float s = 0.f;
    #pragma unroll
    for (int o = 0; o < OO; o++) s += p[(long)o * HIDC * PHW];
    S[idx] = roundtf(s);
}
// enc per-object: states = round(relu(base + conv3x3(mask, enc_w[:,256])))
__global__ void __launch_bounds__(256) enc_obj_k(
    const float* __restrict__ masks, const float* __restrict__ enc_w,
    const float* __restrict__ pbase, float* __restrict__ pst)
{
    __shared__ float wm[HIDC * 9];
    const int tid = threadIdx.x;
    const int img = blockIdx.y;
    const int p   = blockIdx.x * 256 + tid;
    for (int t = tid; t < HIDC * 9; t += 256) {
        int oc = t / 9, k = t - oc * 9;
        wm[t] = enc_w[((long)oc * 257 + 256) * 9 + k];
    }
    __syncthreads();
    const int y = p >> 6, x = p & 63;
    float m[3][3];
    #pragma unroll
    for (int i = 0; i < 3; i++)
        #pragma unroll
        for (int j = 0; j < 3; j++) {
            int gy = y - 1 + i, gx = x - 1 + j;
            m[i][j] = ((unsigned)gy < 64u && (unsigned)gx < 64u)
                        ? masks[(long)img * HW + gy * 64 + gx] : 0.f;
        }
    const int b = img >> 3;
    const int pp = (y + 1) * PW + x + 1;
    const float* bimg = pbase + (long)b * HIDC * PHW;
    float* simg = pst + (long)img * HIDC * PHW;
    #pragma unroll 4
    for (int oc = 0; oc < HIDC; oc++) {
        float a = bimg[oc * PHW + pp];
        #pragma unroll
        for (int k = 0; k < 9; k++) a = fmaf(wm[oc * 9 + k], m[k / 3][k % 3], a);
        simg[oc * PHW + pp] = roundtf(fmaxf(a, 0.f));
    }
}
// readout base partials: rpart[slice][b] = (slice==0 ? ro_b : 0) +
//   conv3x3(feats[slice*64 .. +63], ro_w slice). grid (16, BB, 4)
__global__ void __launch_bounds__(256) ro_base_k(
    const float* __restrict__ feats, const float* __restrict__ ro_w,
    const float* __restrict__ ro_b, float* __restrict__ rpart)
{
    __shared__ float tile[18 * 18];
    __shared__ float ws[64 * 9];
    const int tid = threadIdx.x;
    const int img = blockIdx.y;
    const int sl  = blockIdx.z;
    const int tx0 = (blockIdx.x & 3) * 16, ty0 = (blockIdx.x >> 2) * 16;
    for (int t = tid; t < 64 * 9; t += 256) ws[t] = ro_w[sl * 64 * 9 + t];
    const int px = tid & 15, py = tid >> 4;
    float acc = (sl == 0) ? ro_b[0] : 0.f;
    const float* fimg = feats + ((long)img * CC + sl * 64) * HW;
    for (int ic = 0; ic < 64; ic++) {
        __syncthreads();
        for (int t = tid; t < 18 * 18; t += 256) {
            int yy = t / 18, xx = t - yy * 18;
            int gy = ty0 - 1 + yy, gx = tx0 - 1 + xx;
            tile[t] = ((unsigned)gy < 64u && (unsigned)gx < 64u)
                        ? fimg[(long)ic * HW + gy * 64 + gx] : 0.f;
        }
        __syncthreads();
        #pragma unroll
        for (int k = 0; k < 9; k++)
            acc = fmaf(ws[ic * 9 + k], tile[(py + k / 3) * 18 + px + (k % 3)], acc);
    }
    rpart[((long)sl * BB + img) * HW + (ty0 + py) * 64 + tx0 + px] = acc;
}
// readout per-object (padded, unrounded final states in)
__global__ void __launch_bounds__(256) ro_obj_k(
    const float* __restrict__ pst, const float* __restrict__ ro_w,
    const float* __restrict__ rpart, float* __restrict__ outp)
{
    __shared__ float tile[18 * 18];
    __shared__ float ws[HIDC * 9];
    const int tid = threadIdx.x;
    const int img = blockIdx.y;
    const int tx0 = (blockIdx.x & 3) * 16, ty0 = (blockIdx.x >> 2) * 16;
    for (int t = tid; t < HIDC * 9; t += 256) ws[t] = ro_w[(long)CC * 9 + t];
    const int px = tid & 15, py = tid >> 4;
    float acc = 0.f;
    const float* simg = pst + (long)img * HIDC * PHW;
    for (int ic = 0; ic < HIDC; ic++) {
        __syncthreads();
        for (int t = tid; t < 18 * 18; t += 256) {
            int yy = t / 18, xx = t - yy * 18;
            tile[t] = simg[(long)ic * PHW + (ty0 + yy) * PW + tx0 + xx];
        }
        __syncthreads();
        #pragma unroll
        for (int k = 0; k < 9; k++)
            acc = fmaf(ws[ic * 9 + k], tile[(py + k / 3) * 18 + px + (k % 3)], acc);
    }
    const int b = img >> 3;
    const long po = (long)b * HW + (ty0 + py) * 64 + tx0 + px;
    float z = acc + rpart[po] + rpart[(long)BB * HW + po]
              + rpart[2L * BB * HW + po] + rpart[3L * BB * HW + po];
    outp[(long)img * HW + (ty0 + py) * 64 + tx0 + px] = 1.f / (1.f + expf(-z));
}

// ---------------------------------------------------------------------------
extern "C" void kernel_launch(void* const* d_in, const int* in_sizes, int n_in,
                              void* d_out, int out_size)
{
    const float* feats = (const float*)d_in[0];
    const float* masks = (const float*)d_in[1];
    const float* enc_w = (const float*)d_in[4];
    const float* enc_b = (const float*)d_in[5];
    const float* gcn_w = (const float*)d_in[6];
    const float* gcn_b = (const float*)d_in[7];
    const float* ro_w  = (const float*)d_in[8];
    const float* ro_b  = (const float*)d_in[9];
    float* outp = (float*)d_out;

    float *pst0, *pst1, *pS, *pfeats, *pbase, *T, *rpart, *wencp, *w2p, *wdp;
    cudaGetSymbolAddress((void**)&pst0,   g_pst0);
    cudaGetSymbolAddress((void**)&pst1,   g_pst1);
    cudaGetSymbolAddress((void**)&pS,     g_pS);
    cudaGetSymbolAddress((void**)&pfeats, g_pfeats);
    cudaGetSymbolAddress((void**)&pbase,  g_pbase);
    cudaGetSymbolAddress((void**)&T,      g_T);
    cudaGetSymbolAddress((void**)&rpart,  g_rpart);
    cudaGetSymbolAddress((void**)&wencp,  g_wencp);
    cudaGetSymbolAddress((void**)&w2p,    g_w2p);
    cudaGetSymbolAddress((void**)&wdp,    g_wdp);

    cudaFuncSetAttribute(conv_mma<128>,
                         cudaFuncAttributeMaxDynamicSharedMemorySize, CONV_DSM);
    cudaFuncSetAttribute(conv_mma<256>,
                         cudaFuncAttributeMaxDynamicSharedMemorySize, CONV_DSM);

    prep_enc_pack<<<(HIDC*CC*9 + 255)/256, 256>>>(enc_w, wencp);
    prep_gcn_pack<<<(HIDC*HIDC*9 + 255)/256, 256>>>(gcn_w, w2p, wdp);
    pad_feats_k<<<(int)(((long)BB*CC*PHW + 255)/256), 256>>>(feats, pfeats);

    // enc base: conv(pfeats, enc_w[:, :256]) + enc_b -> padded base (fp32)
    conv_mma<256><<<dim3(32, BB), 256, CONV_DSM>>>(pfeats, wencp, enc_b,
                                                   nullptr, 0, pbase, 1, 0, 0);
    // enc per-object (stores rounded states)
    enc_obj_k<<<dim3(16, BB*OO), 256>>>(masks, enc_w, pbase, pst0);

    float* cur = pst0; float* nxt = pst1;
    for (int s = 0; s < 2; s++) {
        sumO_k<<<(int)(((long)BB*HIDC*PHW + 255)/256), 256>>>(cur, pS);
        // T = conv(S, W2) + gcn_b (unpadded fp32 out)
        conv_mma<128><<<dim3(32, BB), 256, CONV_DSM>>>(pS, w2p, gcn_b,
                                                       nullptr, 0, T, 0, 0, 0);
        // states' = relu(conv(states, Wd) + T); round unless final step
        conv_mma<128><<<dim3(32, BB*OO), 256, CONV_DSM>>>(cur, wdp, nullptr,
                                                          T, OO, nxt, 1, 1,
                                                          s == 0 ? 1 : 0);
        float* tmp = cur; cur = nxt; nxt = tmp;
    }

    ro_base_k<<<dim3(16, BB, 4), 256>>>(feats, ro_w, ro_b, rpart);
    ro_obj_k<<<dim3(16, BB*OO), 256>>>(cur, ro_w, rpart, outp);
}